// round 13
// baseline (speedup 1.0000x reference)
#include <cuda_runtime.h>
#include <cuda_fp16.h>
#include <cstdint>

#define BTOT 8
#define CIN  384
#define HWSZ 4096
#define DDIM 128
#define NTOK 512
#define MROW (BTOT*HWSZ)   // 32768
#define KSEL 81
#define LN_EPS 1e-5f

#define OUT_MASK 0
#define OUT_IMG  32768
#define OUT_RES  (32768 + BTOT*CIN*HWSZ)

// ---------------- scratch ----------------
__device__ __half g_W2hi[DDIM*CIN];
__device__ __half g_W2lo[DDIM*CIN];
__device__ float g_b2[DDIM];
__device__ __half g_wouthi[CIN*DDIM];
__device__ __half g_dr_hi[NTOK*DDIM];
__device__ __half g_dr_lo[NTOK*DDIM];
__device__ float g_rn[NTOK];
__device__ float g_simE[(size_t)MROW*NTOK];
__device__ float g_rowinv[MROW];
__device__ float g_rowmax[MROW];
__device__ int   g_topidx[BTOT*KSEL];

// ---------------- helpers ----------------
__device__ __forceinline__ uint32_t smem_u32(const void* p){
    uint32_t a; asm("{ .reg .u64 t; cvta.to.shared.u64 t, %1; cvt.u32.u64 %0, t; }" : "=r"(a) : "l"(p));
    return a;
}
__device__ __forceinline__ void ldmx4(uint32_t* r, uint32_t addr){
    asm volatile("ldmatrix.sync.aligned.m8n8.x4.shared.b16 {%0,%1,%2,%3}, [%4];"
        : "=r"(r[0]),"=r"(r[1]),"=r"(r[2]),"=r"(r[3]) : "r"(addr));
}
__device__ __forceinline__ void ldmx4t(uint32_t* r, uint32_t addr){
    asm volatile("ldmatrix.sync.aligned.m8n8.x4.trans.shared.b16 {%0,%1,%2,%3}, [%4];"
        : "=r"(r[0]),"=r"(r[1]),"=r"(r[2]),"=r"(r[3]) : "r"(addr));
}
__device__ __forceinline__ void mma16816(float* c, const uint32_t* a, const uint32_t* b){
    asm volatile("mma.sync.aligned.m16n8k16.row.col.f32.f16.f16.f32 "
        "{%0,%1,%2,%3},{%4,%5,%6,%7},{%8,%9},{%0,%1,%2,%3};"
        : "+f"(c[0]),"+f"(c[1]),"+f"(c[2]),"+f"(c[3])
        : "r"(a[0]),"r"(a[1]),"r"(a[2]),"r"(a[3]),"r"(b[0]),"r"(b[1]));
}
__device__ __forceinline__ uint32_t pack_h2(float a, float b){
    __half2 t = __floats2half2_rn(a,b);
    return *(uint32_t*)&t;
}
// stage 128x128 f16 tile to smem (272B pitch) -- 256 threads
__device__ __forceinline__ void stage136(char* dst, const __half* __restrict__ src, int stride){
    int t = threadIdx.x;
    #pragma unroll
    for (int i = 0; i < 8; i++){
        int idx = t + (i<<8);
        int row = idx >> 4, c8 = (idx & 15) << 3;
        *(uint4*)(dst + row*272 + c8*2) = *(const uint4*)(src + (size_t)row*stride + c8);
    }
}
__device__ __forceinline__ uint32_t aAddr(uint32_t tileBase, int k0, int lane){
    return tileBase + (uint32_t)(lane & 15)*272u + (uint32_t)(k0 + ((lane>>4)<<3))*2u;
}
__device__ __forceinline__ uint32_t aTAddr(uint32_t base, int m0, int k0, int lane){
    int row = k0 + ((lane>>4)<<3) + (lane&7);
    int col = m0 + (((lane>>3)&1)<<3);
    return base + (uint32_t)row*272u + (uint32_t)col*2u;
}
__device__ __forceinline__ uint32_t bAddr4(uint32_t base, int n0, int k0, int lane){
    int row = n0 + ((lane>>4)<<3) + (lane&7);
    int col = k0 + ((lane>>3)&1)*8;
    return base + (uint32_t)row*272u + (uint32_t)col*2u;
}
__device__ __forceinline__ uint32_t bTAddr4(uint32_t base, int n0, int k0, int lane){
    int row = k0 + ((lane>>3)&1)*8 + (lane&7);
    int col = n0 + ((lane>>4)<<3);
    return base + (uint32_t)row*272u + (uint32_t)col*2u;
}
__device__ __forceinline__ float wSum(float v){
    #pragma unroll
    for (int o=16;o;o>>=1) v += __shfl_xor_sync(0xFFFFFFFFu, v, o);
    return v;
}
__device__ __forceinline__ float wMaxF(float v){
    #pragma unroll
    for (int o=16;o;o>>=1) v = fmaxf(v, __shfl_xor_sync(0xFFFFFFFFu, v, o));
    return v;
}
__device__ __forceinline__ float wMinF(float v){
    #pragma unroll
    for (int o=16;o;o>>=1) v = fminf(v, __shfl_xor_sync(0xFFFFFFFFu, v, o));
    return v;
}
__device__ __forceinline__ float qSum(float v){
    v += __shfl_xor_sync(0xFFFFFFFFu, v, 1);
    v += __shfl_xor_sync(0xFFFFFFFFu, v, 2);
    return v;
}
__device__ __forceinline__ float qMax(float v){
    v = fmaxf(v, __shfl_xor_sync(0xFFFFFFFFu, v, 1));
    v = fmaxf(v, __shfl_xor_sync(0xFFFFFFFFu, v, 2));
    return v;
}

// ---------------- K0: merged prep (W2, wout, DR layernorm) ----------------
__global__ __launch_bounds__(384) void k_prep_all(const float* __restrict__ sw,
                                                  const float* __restrict__ ciw,
                                                  const float* __restrict__ cib,
                                                  const float* __restrict__ semb,
                                                  const float* __restrict__ cow,
                                                  const float* __restrict__ DRp,
                                                  const float* __restrict__ n2w,
                                                  const float* __restrict__ n2b){
    int bid = blockIdx.x, t = threadIdx.x;
    if (bid < 128){
        __shared__ float srow[128];
        int o = bid;
        if (t < 128) srow[t] = sw[o*DDIM + t];
        __syncthreads();
        float acc = 0.f;
        #pragma unroll 4
        for (int d = 0; d < 128; d++) acc += srow[d] * ciw[d*CIN + t];
        __half h = __float2half(acc);
        g_W2hi[o*CIN + t] = h;
        g_W2lo[o*CIN + t] = __float2half(acc - __half2float(h));
        if (t == 0){
            float bacc = 0.f;
            for (int d = 0; d < 128; d++) bacc += srow[d] * cib[d];
            g_b2[o] = bacc + semb[o];
        }
    } else if (bid < 256){
        int id = (bid - 128)*384 + t;
        g_wouthi[id] = __float2half(cow[id]);
    } else {
        int w = t >> 5, lane = t & 31;
        if (w < 8){
            int n = (bid - 256)*8 + w;
            float v[4];
            float s = 0.f;
            #pragma unroll
            for (int i = 0; i < 4; i++){ v[i] = DRp[n*DDIM + lane + (i<<5)]; s += v[i]; }
            float mean = wSum(s) * (1.f/DDIM);
            float q = 0.f;
            #pragma unroll
            for (int i = 0; i < 4; i++){ float d = v[i]-mean; q += d*d; }
            float rstd = rsqrtf(wSum(q)*(1.f/DDIM) + LN_EPS);
            float ln[4]; float ss = 0.f;
            #pragma unroll
            for (int i = 0; i < 4; i++){
                int dd = lane + (i<<5);
                ln[i] = (v[i]-mean)*rstd*n2w[dd] + n2b[dd];
                ss += ln[i]*ln[i];
            }
            ss = wSum(ss);
            #pragma unroll
            for (int i = 0; i < 4; i++){
                int dd = lane + (i<<5);
                __half h = __float2half(ln[i]);
                g_dr_hi[n*DDIM + dd] = h;
                g_dr_lo[n*DDIM + dd] = __float2half(ln[i] - __half2float(h));
            }
            if (lane == 0) g_rn[n] = rsqrtf(ss);
        }
    }
}

// ========== K2: FUSED sem + double-LN + sim + softmax + degrad(2p) + conv_out(2p) ==========
#define SMEM_FUSED (139264 + 3584)
__global__ __launch_bounds__(256,1) void k_fused(const float* __restrict__ x,
                                                 const float* __restrict__ n1w,
                                                 const float* __restrict__ n1b,
                                                 const float* __restrict__ cob,
                                                 float* __restrict__ outp){
    extern __shared__ char smem[];
    uint32_t sb = smem_u32(smem);
    int t = threadIdx.x, lane = t & 31, w = t >> 5;
    int m0 = blockIdx.x * 128;
    int b = m0 >> 12, l0 = m0 & 4095;

    uint32_t o_Ah = sb, o_Al = sb + 34816;
    uint32_t o_Bh = sb + 69632, o_Bl = sb + 104448;
    float* W1v = (float*)(smem + 139264);
    float* B1v = W1v + 128;
    float* b2v = B1v + 128;
    float* rnv = b2v + 128;
    if (t < 128){ W1v[t] = n1w[t]; B1v[t] = n1b[t]; b2v[t] = g_b2[t]; }
    rnv[t] = g_rn[t]; rnv[t+256] = g_rn[t+256];

    const float* xb = x + (size_t)b * CIN * HWSZ + l0;
    float acc[16][4] = {};

    // ===== phase 1: GEMM1, K=384 (3-pass, interleaved acc targets) =====
    for (int ch = 0; ch < 3; ch++){
        if (ch) __syncthreads();
        #pragma unroll
        for (int i = 0; i < 16; i++){
            int id = t + (i<<8);
            int cr = id >> 5;
            int lq = (id & 31) << 2;
            float4 vv = *(const float4*)(xb + (size_t)(ch*128 + cr)*HWSZ + lq);
            float hx = __half2float(__float2half(vv.x));
            float hy = __half2float(__float2half(vv.y));
            float hz = __half2float(__float2half(vv.z));
            float hw = __half2float(__float2half(vv.w));
            *(uint2*)(smem + cr*272 + lq*2) = make_uint2(pack_h2(vv.x, vv.y), pack_h2(vv.z, vv.w));
            *(uint2*)(smem + 34816 + cr*272 + lq*2) = make_uint2(pack_h2(vv.x-hx, vv.y-hy), pack_h2(vv.z-hz, vv.w-hw));
        }
        #pragma unroll
        for (int i = 0; i < 8; i++){
            int idx = t + (i<<8);
            int row = idx >> 4, c8 = (idx & 15) << 3;
            *(uint4*)(smem + 69632  + row*272 + c8*2) = *(const uint4*)(g_W2hi + row*CIN + ch*128 + c8);
            *(uint4*)(smem + 104448 + row*272 + c8*2) = *(const uint4*)(g_W2lo + row*CIN + ch*128 + c8);
        }
        __syncthreads();
        #pragma unroll
        for (int ks = 0; ks < 8; ks++){
            uint32_t ah[4], al[4];
            ldmx4t(ah, aTAddr(o_Ah, w*16, ks*16, lane));
            ldmx4t(al, aTAddr(o_Al, w*16, ks*16, lane));
            #pragma unroll
            for (int j2 = 0; j2 < 8; j2++){
                uint32_t bh[4], bl[4];
                ldmx4(bh, bAddr4(o_Bh, j2*16, ks*16, lane));
                ldmx4(bl, bAddr4(o_Bl, j2*16, ks*16, lane));
                mma16816(acc[2*j2],   ah, bh);
                mma16816(acc[2*j2+1], ah, bh+2);
                mma16816(acc[2*j2],   ah, bl);
                mma16816(acc[2*j2+1], ah, bl+2);
                mma16816(acc[2*j2],   al, bh);
                mma16816(acc[2*j2+1], al, bh+2);
            }
        }
    }
    __syncthreads();

    // ===== double-LN epilogue -> A tile (ln2*cdlinv, f16 hi/lo) =====
    int gid = lane >> 2, tig = lane & 3;
    #pragma unroll
    for (int half = 0; half < 2; half++){
        int rl = w*16 + gid + half*8;
        float v[32];
        #pragma unroll
        for (int j = 0; j < 16; j++){
            int col = j*8 + 2*tig;
            v[2*j]   = acc[j][2*half]   + b2v[col];
            v[2*j+1] = acc[j][2*half+1] + b2v[col+1];
        }
        float s = 0.f;
        #pragma unroll
        for (int k = 0; k < 32; k++) s += v[k];
        float mean = qSum(s) * (1.f/DDIM);
        float q = 0.f;
        #pragma unroll
        for (int k = 0; k < 32; k++){ float d = v[k]-mean; q += d*d; }
        float rstd = rsqrtf(qSum(q)*(1.f/DDIM) + LN_EPS);
        float ln1[32]; float ss = 0.f, s2 = 0.f;
        #pragma unroll
        for (int j = 0; j < 16; j++){
            int col = j*8 + 2*tig;
            #pragma unroll
            for (int u = 0; u < 2; u++){
                float y = (v[2*j+u]-mean)*rstd*W1v[col+u] + B1v[col+u];
                ln1[2*j+u] = y; ss += y*y; s2 += y;
            }
        }
        float cdlinv = rsqrtf(qSum(ss));
        float m2 = qSum(s2) * (1.f/DDIM);
        float q2 = 0.f;
        #pragma unroll
        for (int k = 0; k < 32; k++){ float d = ln1[k]-m2; q2 += d*d; }
        float rstd2 = rsqrtf(qSum(q2)*(1.f/DDIM) + LN_EPS);
        #pragma unroll
        for (int j = 0; j < 16; j++){
            int col = j*8 + 2*tig;
            float y0 = ((ln1[2*j]-m2)*rstd2*W1v[col] + B1v[col]) * cdlinv;
            float y1 = ((ln1[2*j+1]-m2)*rstd2*W1v[col+1] + B1v[col+1]) * cdlinv;
            float h0 = __half2float(__float2half(y0));
            float h1 = __half2float(__float2half(y1));
            *(uint32_t*)(smem + rl*272 + col*2) = pack_h2(y0, y1);
            *(uint32_t*)(smem + 34816 + rl*272 + col*2) = pack_h2(y0-h0, y1-h1);
        }
    }

    // ===== phase 2: sim (3-pass) + softmax + degrad (2-pass) =====
    uint32_t aTh = o_Ah + (uint32_t)(w*16)*272u;
    uint32_t aTl = o_Al + (uint32_t)(w*16)*272u;
    int rlo = m0 + w*16 + gid, rhi = rlo + 8;

    float acc2[16][4] = {};
    float sum_lo = 0.f, sum_hi = 0.f, emax_lo = 0.f, emax_hi = 0.f;

    for (int c = 0; c < 4; c++){
        __syncthreads();
        stage136(smem + 69632,  g_dr_hi + (size_t)c*128*DDIM, DDIM);
        stage136(smem + 104448, g_dr_lo + (size_t)c*128*DDIM, DDIM);
        __syncthreads();

        float acc1[16][4] = {};
        #pragma unroll
        for (int ks = 0; ks < 8; ks++){
            uint32_t ah[4], al[4];
            ldmx4(ah, aAddr(aTh, ks*16, lane));
            ldmx4(al, aAddr(aTl, ks*16, lane));
            #pragma unroll
            for (int j2 = 0; j2 < 8; j2++){
                uint32_t bh[4], bl[4];
                ldmx4(bh, bAddr4(o_Bh, j2*16, ks*16, lane));
                ldmx4(bl, bAddr4(o_Bl, j2*16, ks*16, lane));
                mma16816(acc1[2*j2],   ah, bh);
                mma16816(acc1[2*j2+1], ah, bh+2);
                mma16816(acc1[2*j2],   ah, bl);
                mma16816(acc1[2*j2+1], ah, bl+2);
                mma16816(acc1[2*j2],   al, bh);
                mma16816(acc1[2*j2+1], al, bh+2);
            }
        }

        uint32_t ehi[16][2];
        #pragma unroll
        for (int j = 0; j < 16; j++){
            int coll = j*8 + 2*tig;
            float rn0 = rnv[c*128 + coll], rn1 = rnv[c*128 + coll + 1];
            float e0 = __expf(acc1[j][0]*rn0), e1 = __expf(acc1[j][1]*rn1);
            float e2 = __expf(acc1[j][2]*rn0), e3 = __expf(acc1[j][3]*rn1);
            sum_lo += e0 + e1; sum_hi += e2 + e3;
            emax_lo = fmaxf(emax_lo, fmaxf(e0, e1));
            emax_hi = fmaxf(emax_hi, fmaxf(e2, e3));
            int col = c*128 + coll;
            *(float2*)&g_simE[(size_t)rlo*NTOK + col] = make_float2(e0, e1);
            *(float2*)&g_simE[(size_t)rhi*NTOK + col] = make_float2(e2, e3);
            ehi[j][0] = pack_h2(e0, e1);
            ehi[j][1] = pack_h2(e2, e3);
        }

        #pragma unroll
        for (int k = 0; k < 8; k++){
            uint32_t ah[4] = { ehi[2*k][0], ehi[2*k][1], ehi[2*k+1][0], ehi[2*k+1][1] };
            #pragma unroll
            for (int j4 = 0; j4 < 8; j4++){
                uint32_t bh[4], bl[4];
                ldmx4t(bh, bTAddr4(o_Bh, j4*16, k*16, lane));
                ldmx4t(bl, bTAddr4(o_Bl, j4*16, k*16, lane));
                mma16816(acc2[2*j4],   ah, bh);
                mma16816(acc2[2*j4+1], ah, bh+2);
                mma16816(acc2[2*j4],   ah, bl);
                mma16816(acc2[2*j4+1], ah, bl+2);
            }
        }
    }

    sum_lo = qSum(sum_lo); sum_hi = qSum(sum_hi);
    emax_lo = qMax(emax_lo); emax_hi = qMax(emax_hi);
    float inv_lo = 1.f / sum_lo, inv_hi = 1.f / sum_hi;
    if (tig == 0){
        g_rowinv[rlo] = inv_lo;  g_rowinv[rhi] = inv_hi;
        g_rowmax[rlo] = emax_lo * inv_lo;  g_rowmax[rhi] = emax_hi * inv_hi;
    }
    __syncthreads();

    // degrad -> A slots (f16 hi/lo)
    #pragma unroll
    for (int j2 = 0; j2 < 16; j2++){
        int dcol = j2*8 + 2*tig;
        int rl_lo = w*16 + gid, rl_hi = rl_lo + 8;
        float y0 = acc2[j2][0]*inv_lo, y1 = acc2[j2][1]*inv_lo;
        float y2 = acc2[j2][2]*inv_hi, y3 = acc2[j2][3]*inv_hi;
        float h0 = __half2float(__float2half(y0));
        float h1 = __half2float(__float2half(y1));
        float h2 = __half2float(__float2half(y2));
        float h3 = __half2float(__float2half(y3));
        *(uint32_t*)(smem + rl_lo*272 + dcol*2) = pack_h2(y0, y1);
        *(uint32_t*)(smem + 34816 + rl_lo*272 + dcol*2) = pack_h2(y0-h0, y1-h1);
        *(uint32_t*)(smem + rl_hi*272 + dcol*2) = pack_h2(y2, y3);
        *(uint32_t*)(smem + 34816 + rl_hi*272 + dcol*2) = pack_h2(y2-h2, y3-h3);
    }

    // ===== phase 3: conv_out (2-pass: Whi x (Dhi + Dlo)) =====
    for (int co = 0; co < 3; co++){
        __syncthreads();
        stage136(smem + 69632, g_wouthi + (size_t)(co*128)*DDIM, DDIM);
        __syncthreads();
        float acc3[16][4] = {};
        #pragma unroll
        for (int ks = 0; ks < 8; ks++){
            uint32_t ah[4];
            ldmx4(ah, aAddr(o_Bh + (uint32_t)(w*16)*272u, ks*16, lane));
            #pragma unroll
            for (int j2 = 0; j2 < 8; j2++){
                uint32_t bh[4], bl[4];
                ldmx4(bh, bAddr4(o_Ah, j2*16, ks*16, lane));
                ldmx4(bl, bAddr4(o_Al, j2*16, ks*16, lane));
                mma16816(acc3[2*j2],   ah, bh);
                mma16816(acc3[2*j2+1], ah, bh+2);
                mma16816(acc3[2*j2],   ah, bl);
                mma16816(acc3[2*j2+1], ah, bl+2);
            }
        }
        int orow = co*128 + w*16 + gid;
        float bb0 = __ldg(cob + orow), bb1 = __ldg(cob + orow + 8);
        #pragma unroll
        for (int j = 0; j < 16; j++){
            int col = l0 + j*8 + 2*tig;
            *(float2*)&outp[OUT_IMG + ((size_t)(b*CIN + orow))*HWSZ + col] =
                make_float2(acc3[j][0] + bb0, acc3[j][1] + bb0);
            *(float2*)&outp[OUT_IMG + ((size_t)(b*CIN + orow + 8))*HWSZ + col] =
                make_float2(acc3[j][2] + bb1, acc3[j][3] + bb1);
        }
    }
}

// ---------------- K5: mask + top-81 via radix select ----------------
__global__ __launch_bounds__(1024) void k_topk_mask(float* __restrict__ outp){
    __shared__ uint32_t hist[256];
    __shared__ uint32_t s_prefix;
    __shared__ int s_krem;
    __shared__ float sred[32];
    __shared__ float s_mn, s_mx;
    __shared__ unsigned long long cand[256];
    __shared__ uint32_t s_cnt;
    int b = blockIdx.x, t = threadIdx.x;
    int lane = t & 31, w = t >> 5;
    float v[4];
    float mn = 1e30f, mx = -1e30f;
    #pragma unroll
    for (int i = 0; i < 4; i++){
        v[i] = g_rowmax[b*HWSZ + t + (i<<10)];
        mn = fminf(mn, v[i]); mx = fmaxf(mx, v[i]);
    }
    mn = wMinF(mn);
    if (lane == 0) sred[w] = mn;
    __syncthreads();
    if (w == 0){ float x = wMinF(sred[lane]); if (lane == 0) s_mn = x; }
    __syncthreads();
    mx = wMaxF(mx);
    if (lane == 0) sred[w] = mx;
    __syncthreads();
    if (w == 0){ float x = wMaxF(sred[lane]); if (lane == 0) s_mx = x; }
    __syncthreads();
    float mn3 = s_mn*s_mn*s_mn, mx3 = s_mx*s_mx*s_mx;
    float inv = 1.f / (mx3 - mn3);
    #pragma unroll
    for (int i = 0; i < 4; i++){
        int l = t + (i<<10);
        outp[OUT_MASK + b*HWSZ + l] = 1.f - (v[i]*v[i]*v[i] - mn3) * inv;
    }

    uint32_t kb[4];
    #pragma unroll
    for (int i = 0; i < 4; i++) kb[i] = __float_as_uint(v[i]);

    if (t == 0){ s_prefix = 0u; s_krem = KSEL; s_cnt = 0u; }

    #pragma unroll
    for (int round = 0; round < 4; round++){
        int shift = 24 - 8*round;
        uint32_t pm = (round == 0) ? 0u : (0xFFFFFFFFu << (32 - 8*round));
        if (t < 256) hist[t] = 0;
        __syncthreads();
        uint32_t P = s_prefix;
        #pragma unroll
        for (int i = 0; i < 4; i++)
            if ((kb[i] & pm) == P) atomicAdd(&hist[(kb[i] >> shift) & 255], 1);
        __syncthreads();
        if (w == 0){
            uint32_t loc[8]; uint32_t ls = 0;
            #pragma unroll
            for (int j = 0; j < 8; j++){ loc[j] = hist[lane*8 + j]; ls += loc[j]; }
            uint32_t incl = ls;
            #pragma unroll
            for (int o = 1; o < 32; o <<= 1){
                uint32_t u = __shfl_down_sync(0xFFFFFFFFu, incl, o);
                if (lane + o < 32) incl += u;
            }
            uint32_t H = incl - ls;
            int krem = s_krem;
            if ((int)H < krem && krem <= (int)incl){
                uint32_t cum = H;
                #pragma unroll
                for (int j = 7; j >= 0; j--){
                    uint32_t above = cum;
                    cum += loc[j];
                    if ((int)above < krem && krem <= (int)cum){
                        s_prefix = s_prefix | ((uint32_t)(lane*8 + j) << shift);
                        s_krem = krem - (int)above;
                        break;
                    }
                }
            }
        }
        __syncthreads();
    }

    uint32_t T = s_prefix;
    #pragma unroll
    for (int i = 0; i < 4; i++){
        if (kb[i] >= T){
            int l = t + (i<<10);
            uint32_t pos = atomicAdd(&s_cnt, 1u);
            if (pos < 256)
                cand[pos] = ((unsigned long long)kb[i] << 32) | (unsigned)(0xFFFFFFFFu - (unsigned)l);
        }
    }
    __syncthreads();
    int S = (int)s_cnt; if (S > 256) S = 256;
    if (t < S){
        unsigned long long key = cand[t];
        int rank = 0;
        for (int j = 0; j < S; j++) rank += (cand[j] > key);
        if (rank < KSEL)
            g_topidx[b*KSEL + rank] = (int)(0xFFFFFFFFu - (unsigned)(key & 0xFFFFFFFFull));
    }
}

// ---------------- K7: gather ----------------
__global__ __launch_bounds__(128) void k_gather(float* __restrict__ outp){
    int g = blockIdx.x;
    int b = g / (BTOT*KSEL);
    int rem = g - b*(BTOT*KSEL);
    int i = rem / KSEL, k = rem - i*KSEL;
    int src = g_topidx[i*KSEL + k];
    size_t row = (size_t)(b*HWSZ + src);
    float inv = g_rowinv[row];
    const float4* s = (const float4*)&g_simE[row*NTOK];
    float4* o = (float4*)&outp[OUT_RES + (size_t)g*NTOK];
    float4 vv = s[threadIdx.x];
    vv.x *= inv; vv.y *= inv; vv.z *= inv; vv.w *= inv;
    o[threadIdx.x] = vv;
}

// ---------------- launch ----------------
extern "C" void kernel_launch(void* const* d_in, const int* in_sizes, int n_in,
                              void* d_out, int out_size){
    const float* x   = (const float*)d_in[0];
    const float* DRp = (const float*)d_in[1];
    const float* ciw = (const float*)d_in[2];
    const float* cib = (const float*)d_in[3];
    const float* sw  = (const float*)d_in[4];
    const float* sb  = (const float*)d_in[5];
    const float* n1w = (const float*)d_in[6];
    const float* n1b = (const float*)d_in[7];
    const float* n2w = (const float*)d_in[8];
    const float* n2b = (const float*)d_in[9];
    const float* cow = (const float*)d_in[10];
    const float* cob = (const float*)d_in[11];
    float* out = (float*)d_out;

    cudaFuncSetAttribute(k_fused, cudaFuncAttributeMaxDynamicSharedMemorySize, SMEM_FUSED);

    k_prep_all <<<320, 384>>>(sw, ciw, cib, sb, cow, DRp, n2w, n2b);
    k_fused    <<<MROW/128, 256, SMEM_FUSED>>>(x, n1w, n1b, cob, out);
    k_topk_mask<<<BTOT, 1024>>>(out);
    k_gather   <<<BTOT*BTOT*KSEL, 128>>>(out);
}

// round 14
// speedup vs baseline: 1.1088x; 1.1088x over previous
#include <cuda_runtime.h>
#include <cuda_fp16.h>
#include <cstdint>

#define BTOT 8
#define CIN  384
#define HWSZ 4096
#define DDIM 128
#define NTOK 512
#define MROW (BTOT*HWSZ)   // 32768
#define KSEL 81
#define LN_EPS 1e-5f

#define OUT_MASK 0
#define OUT_IMG  32768
#define OUT_RES  (32768 + BTOT*CIN*HWSZ)

// ---------------- scratch ----------------
__device__ __half g_W2hi[DDIM*CIN];
__device__ __half g_W2lo[DDIM*CIN];
__device__ float g_b2[DDIM];
__device__ __half g_wouthi[CIN*DDIM];
__device__ __half g_dr_hi[NTOK*DDIM];
__device__ __half g_dr_lo[NTOK*DDIM];
__device__ float g_rn[NTOK];
__device__ float g_simE[(size_t)MROW*NTOK];
__device__ float g_rowinv[MROW];
__device__ float g_rowmax[MROW];
__device__ int   g_topidx[BTOT*KSEL];

// ---------------- helpers ----------------
__device__ __forceinline__ uint32_t smem_u32(const void* p){
    uint32_t a; asm("{ .reg .u64 t; cvta.to.shared.u64 t, %1; cvt.u32.u64 %0, t; }" : "=r"(a) : "l"(p));
    return a;
}
__device__ __forceinline__ void ldmx4(uint32_t* r, uint32_t addr){
    asm volatile("ldmatrix.sync.aligned.m8n8.x4.shared.b16 {%0,%1,%2,%3}, [%4];"
        : "=r"(r[0]),"=r"(r[1]),"=r"(r[2]),"=r"(r[3]) : "r"(addr));
}
__device__ __forceinline__ void ldmx4t(uint32_t* r, uint32_t addr){
    asm volatile("ldmatrix.sync.aligned.m8n8.x4.trans.shared.b16 {%0,%1,%2,%3}, [%4];"
        : "=r"(r[0]),"=r"(r[1]),"=r"(r[2]),"=r"(r[3]) : "r"(addr));
}
__device__ __forceinline__ void mma16816(float* c, const uint32_t* a, const uint32_t* b){
    asm volatile("mma.sync.aligned.m16n8k16.row.col.f32.f16.f16.f32 "
        "{%0,%1,%2,%3},{%4,%5,%6,%7},{%8,%9},{%0,%1,%2,%3};"
        : "+f"(c[0]),"+f"(c[1]),"+f"(c[2]),"+f"(c[3])
        : "r"(a[0]),"r"(a[1]),"r"(a[2]),"r"(a[3]),"r"(b[0]),"r"(b[1]));
}
__device__ __forceinline__ uint32_t pack_h2(float a, float b){
    __half2 t = __floats2half2_rn(a,b);
    return *(uint32_t*)&t;
}
// stage 128x128 f16 tile to smem (272B pitch) -- 256 threads
__device__ __forceinline__ void stage136(char* dst, const __half* __restrict__ src, int stride){
    int t = threadIdx.x;
    #pragma unroll
    for (int i = 0; i < 8; i++){
        int idx = t + (i<<8);
        int row = idx >> 4, c8 = (idx & 15) << 3;
        *(uint4*)(dst + row*272 + c8*2) = *(const uint4*)(src + (size_t)row*stride + c8);
    }
}
__device__ __forceinline__ uint32_t aAddr(uint32_t tileBase, int k0, int lane){
    return tileBase + (uint32_t)(lane & 15)*272u + (uint32_t)(k0 + ((lane>>4)<<3))*2u;
}
__device__ __forceinline__ uint32_t aTAddr(uint32_t base, int m0, int k0, int lane){
    int row = k0 + ((lane>>4)<<3) + (lane&7);
    int col = m0 + (((lane>>3)&1)<<3);
    return base + (uint32_t)row*272u + (uint32_t)col*2u;
}
__device__ __forceinline__ uint32_t bAddr4(uint32_t base, int n0, int k0, int lane){
    int row = n0 + ((lane>>4)<<3) + (lane&7);
    int col = k0 + ((lane>>3)&1)*8;
    return base + (uint32_t)row*272u + (uint32_t)col*2u;
}
__device__ __forceinline__ uint32_t bTAddr4(uint32_t base, int n0, int k0, int lane){
    int row = k0 + ((lane>>3)&1)*8 + (lane&7);
    int col = n0 + ((lane>>4)<<3);
    return base + (uint32_t)row*272u + (uint32_t)col*2u;
}
__device__ __forceinline__ float wSum(float v){
    #pragma unroll
    for (int o=16;o;o>>=1) v += __shfl_xor_sync(0xFFFFFFFFu, v, o);
    return v;
}
__device__ __forceinline__ float wMaxF(float v){
    #pragma unroll
    for (int o=16;o;o>>=1) v = fmaxf(v, __shfl_xor_sync(0xFFFFFFFFu, v, o));
    return v;
}
__device__ __forceinline__ float wMinF(float v){
    #pragma unroll
    for (int o=16;o;o>>=1) v = fminf(v, __shfl_xor_sync(0xFFFFFFFFu, v, o));
    return v;
}
__device__ __forceinline__ float qSum(float v){
    v += __shfl_xor_sync(0xFFFFFFFFu, v, 1);
    v += __shfl_xor_sync(0xFFFFFFFFu, v, 2);
    return v;
}
__device__ __forceinline__ float qMax(float v){
    v = fmaxf(v, __shfl_xor_sync(0xFFFFFFFFu, v, 1));
    v = fmaxf(v, __shfl_xor_sync(0xFFFFFFFFu, v, 2));
    return v;
}

// ---------------- K0: merged prep (W2, wout, DR layernorm) ----------------
__global__ __launch_bounds__(384) void k_prep_all(const float* __restrict__ sw,
                                                  const float* __restrict__ ciw,
                                                  const float* __restrict__ cib,
                                                  const float* __restrict__ semb,
                                                  const float* __restrict__ cow,
                                                  const float* __restrict__ DRp,
                                                  const float* __restrict__ n2w,
                                                  const float* __restrict__ n2b){
    int bid = blockIdx.x, t = threadIdx.x;
    if (bid < 128){
        __shared__ float srow[128];
        int o = bid;
        if (t < 128) srow[t] = sw[o*DDIM + t];
        __syncthreads();
        float acc = 0.f;
        #pragma unroll 4
        for (int d = 0; d < 128; d++) acc += srow[d] * ciw[d*CIN + t];
        __half h = __float2half(acc);
        g_W2hi[o*CIN + t] = h;
        g_W2lo[o*CIN + t] = __float2half(acc - __half2float(h));
        if (t == 0){
            float bacc = 0.f;
            for (int d = 0; d < 128; d++) bacc += srow[d] * cib[d];
            g_b2[o] = bacc + semb[o];
        }
    } else if (bid < 256){
        int id = (bid - 128)*384 + t;
        g_wouthi[id] = __float2half(cow[id]);
    } else {
        int w = t >> 5, lane = t & 31;
        if (w < 8){
            int n = (bid - 256)*8 + w;
            float v[4];
            float s = 0.f;
            #pragma unroll
            for (int i = 0; i < 4; i++){ v[i] = DRp[n*DDIM + lane + (i<<5)]; s += v[i]; }
            float mean = wSum(s) * (1.f/DDIM);
            float q = 0.f;
            #pragma unroll
            for (int i = 0; i < 4; i++){ float d = v[i]-mean; q += d*d; }
            float rstd = rsqrtf(wSum(q)*(1.f/DDIM) + LN_EPS);
            float ln[4]; float ss = 0.f;
            #pragma unroll
            for (int i = 0; i < 4; i++){
                int dd = lane + (i<<5);
                ln[i] = (v[i]-mean)*rstd*n2w[dd] + n2b[dd];
                ss += ln[i]*ln[i];
            }
            ss = wSum(ss);
            #pragma unroll
            for (int i = 0; i < 4; i++){
                int dd = lane + (i<<5);
                __half h = __float2half(ln[i]);
                g_dr_hi[n*DDIM + dd] = h;
                g_dr_lo[n*DDIM + dd] = __float2half(ln[i] - __half2float(h));
            }
            if (lane == 0) g_rn[n] = rsqrtf(ss);
        }
    }
}

// ========== K2: FUSED sem + double-LN + sim + softmax + degrad(1p) + conv_out(1p) ==========
#define SMEM_FUSED (139264 + 3584)
__global__ __launch_bounds__(256,1) void k_fused(const float* __restrict__ x,
                                                 const float* __restrict__ n1w,
                                                 const float* __restrict__ n1b,
                                                 const float* __restrict__ cob,
                                                 float* __restrict__ outp){
    extern __shared__ char smem[];
    uint32_t sb = smem_u32(smem);
    int t = threadIdx.x, lane = t & 31, w = t >> 5;
    int m0 = blockIdx.x * 128;
    int b = m0 >> 12, l0 = m0 & 4095;

    uint32_t o_Ah = sb, o_Al = sb + 34816;
    uint32_t o_Bh = sb + 69632, o_Bl = sb + 104448;
    float* W1v = (float*)(smem + 139264);
    float* B1v = W1v + 128;
    float* b2v = B1v + 128;
    float* rnv = b2v + 128;
    if (t < 128){ W1v[t] = n1w[t]; B1v[t] = n1b[t]; b2v[t] = g_b2[t]; }
    rnv[t] = g_rn[t]; rnv[t+256] = g_rn[t+256];

    const float* xb = x + (size_t)b * CIN * HWSZ + l0;
    float acc[16][4] = {};

    // ===== phase 1: GEMM1, K=384 (3-pass) =====
    for (int ch = 0; ch < 3; ch++){
        if (ch) __syncthreads();
        #pragma unroll
        for (int i = 0; i < 16; i++){
            int id = t + (i<<8);
            int cr = id >> 5;
            int lq = (id & 31) << 2;
            float4 vv = *(const float4*)(xb + (size_t)(ch*128 + cr)*HWSZ + lq);
            float hx = __half2float(__float2half(vv.x));
            float hy = __half2float(__float2half(vv.y));
            float hz = __half2float(__float2half(vv.z));
            float hw = __half2float(__float2half(vv.w));
            *(uint2*)(smem + cr*272 + lq*2) = make_uint2(pack_h2(vv.x, vv.y), pack_h2(vv.z, vv.w));
            *(uint2*)(smem + 34816 + cr*272 + lq*2) = make_uint2(pack_h2(vv.x-hx, vv.y-hy), pack_h2(vv.z-hz, vv.w-hw));
        }
        #pragma unroll
        for (int i = 0; i < 8; i++){
            int idx = t + (i<<8);
            int row = idx >> 4, c8 = (idx & 15) << 3;
            *(uint4*)(smem + 69632  + row*272 + c8*2) = *(const uint4*)(g_W2hi + row*CIN + ch*128 + c8);
            *(uint4*)(smem + 104448 + row*272 + c8*2) = *(const uint4*)(g_W2lo + row*CIN + ch*128 + c8);
        }
        __syncthreads();
        #pragma unroll
        for (int ks = 0; ks < 8; ks++){
            uint32_t ah[4], al[4];
            ldmx4t(ah, aTAddr(o_Ah, w*16, ks*16, lane));
            ldmx4t(al, aTAddr(o_Al, w*16, ks*16, lane));
            #pragma unroll
            for (int j2 = 0; j2 < 8; j2++){
                uint32_t bh[4], bl[4];
                ldmx4(bh, bAddr4(o_Bh, j2*16, ks*16, lane));
                ldmx4(bl, bAddr4(o_Bl, j2*16, ks*16, lane));
                mma16816(acc[2*j2],   ah, bh);
                mma16816(acc[2*j2+1], ah, bh+2);
                mma16816(acc[2*j2],   ah, bl);
                mma16816(acc[2*j2+1], ah, bl+2);
                mma16816(acc[2*j2],   al, bh);
                mma16816(acc[2*j2+1], al, bh+2);
            }
        }
    }
    __syncthreads();

    // ===== double-LN epilogue -> A tile (ln2*cdlinv, f16 hi/lo) =====
    int gid = lane >> 2, tig = lane & 3;
    #pragma unroll
    for (int half = 0; half < 2; half++){
        int rl = w*16 + gid + half*8;
        float v[32];
        #pragma unroll
        for (int j = 0; j < 16; j++){
            int col = j*8 + 2*tig;
            v[2*j]   = acc[j][2*half]   + b2v[col];
            v[2*j+1] = acc[j][2*half+1] + b2v[col+1];
        }
        float s = 0.f;
        #pragma unroll
        for (int k = 0; k < 32; k++) s += v[k];
        float mean = qSum(s) * (1.f/DDIM);
        float q = 0.f;
        #pragma unroll
        for (int k = 0; k < 32; k++){ float d = v[k]-mean; q += d*d; }
        float rstd = rsqrtf(qSum(q)*(1.f/DDIM) + LN_EPS);
        float ln1[32]; float ss = 0.f, s2 = 0.f;
        #pragma unroll
        for (int j = 0; j < 16; j++){
            int col = j*8 + 2*tig;
            #pragma unroll
            for (int u = 0; u < 2; u++){
                float y = (v[2*j+u]-mean)*rstd*W1v[col+u] + B1v[col+u];
                ln1[2*j+u] = y; ss += y*y; s2 += y;
            }
        }
        float cdlinv = rsqrtf(qSum(ss));
        float m2 = qSum(s2) * (1.f/DDIM);
        float q2 = 0.f;
        #pragma unroll
        for (int k = 0; k < 32; k++){ float d = ln1[k]-m2; q2 += d*d; }
        float rstd2 = rsqrtf(qSum(q2)*(1.f/DDIM) + LN_EPS);
        #pragma unroll
        for (int j = 0; j < 16; j++){
            int col = j*8 + 2*tig;
            float y0 = ((ln1[2*j]-m2)*rstd2*W1v[col] + B1v[col]) * cdlinv;
            float y1 = ((ln1[2*j+1]-m2)*rstd2*W1v[col+1] + B1v[col+1]) * cdlinv;
            float h0 = __half2float(__float2half(y0));
            float h1 = __half2float(__float2half(y1));
            *(uint32_t*)(smem + rl*272 + col*2) = pack_h2(y0, y1);
            *(uint32_t*)(smem + 34816 + rl*272 + col*2) = pack_h2(y0-h0, y1-h1);
        }
    }

    // ===== phase 2: sim (3-pass) + softmax + degrad (1-pass, Phi x drhi) =====
    uint32_t aTh = o_Ah + (uint32_t)(w*16)*272u;
    uint32_t aTl = o_Al + (uint32_t)(w*16)*272u;
    int rlo = m0 + w*16 + gid, rhi = rlo + 8;

    float acc2[16][4] = {};
    float sum_lo = 0.f, sum_hi = 0.f, emax_lo = 0.f, emax_hi = 0.f;

    for (int c = 0; c < 4; c++){
        __syncthreads();
        stage136(smem + 69632,  g_dr_hi + (size_t)c*128*DDIM, DDIM);
        stage136(smem + 104448, g_dr_lo + (size_t)c*128*DDIM, DDIM);
        __syncthreads();

        float acc1[16][4] = {};
        #pragma unroll
        for (int ks = 0; ks < 8; ks++){
            uint32_t ah[4], al[4];
            ldmx4(ah, aAddr(aTh, ks*16, lane));
            ldmx4(al, aAddr(aTl, ks*16, lane));
            #pragma unroll
            for (int j2 = 0; j2 < 8; j2++){
                uint32_t bh[4], bl[4];
                ldmx4(bh, bAddr4(o_Bh, j2*16, ks*16, lane));
                ldmx4(bl, bAddr4(o_Bl, j2*16, ks*16, lane));
                mma16816(acc1[2*j2],   ah, bh);
                mma16816(acc1[2*j2+1], ah, bh+2);
                mma16816(acc1[2*j2],   ah, bl);
                mma16816(acc1[2*j2+1], ah, bl+2);
                mma16816(acc1[2*j2],   al, bh);
                mma16816(acc1[2*j2+1], al, bh+2);
            }
        }

        uint32_t ehi[16][2];
        #pragma unroll
        for (int j = 0; j < 16; j++){
            int coll = j*8 + 2*tig;
            float rn0 = rnv[c*128 + coll], rn1 = rnv[c*128 + coll + 1];
            float e0 = __expf(acc1[j][0]*rn0), e1 = __expf(acc1[j][1]*rn1);
            float e2 = __expf(acc1[j][2]*rn0), e3 = __expf(acc1[j][3]*rn1);
            sum_lo += e0 + e1; sum_hi += e2 + e3;
            emax_lo = fmaxf(emax_lo, fmaxf(e0, e1));
            emax_hi = fmaxf(emax_hi, fmaxf(e2, e3));
            int col = c*128 + coll;
            *(float2*)&g_simE[(size_t)rlo*NTOK + col] = make_float2(e0, e1);
            *(float2*)&g_simE[(size_t)rhi*NTOK + col] = make_float2(e2, e3);
            ehi[j][0] = pack_h2(e0, e1);
            ehi[j][1] = pack_h2(e2, e3);
        }

        // degrad: 1-pass (P_hi x dr_hi)
        #pragma unroll
        for (int k = 0; k < 8; k++){
            uint32_t ah[4] = { ehi[2*k][0], ehi[2*k][1], ehi[2*k+1][0], ehi[2*k+1][1] };
            #pragma unroll
            for (int j4 = 0; j4 < 8; j4++){
                uint32_t bh[4];
                ldmx4t(bh, bTAddr4(o_Bh, j4*16, k*16, lane));
                mma16816(acc2[2*j4],   ah, bh);
                mma16816(acc2[2*j4+1], ah, bh+2);
            }
        }
    }

    sum_lo = qSum(sum_lo); sum_hi = qSum(sum_hi);
    emax_lo = qMax(emax_lo); emax_hi = qMax(emax_hi);
    float inv_lo = 1.f / sum_lo, inv_hi = 1.f / sum_hi;
    if (tig == 0){
        g_rowinv[rlo] = inv_lo;  g_rowinv[rhi] = inv_hi;
        g_rowmax[rlo] = emax_lo * inv_lo;  g_rowmax[rhi] = emax_hi * inv_hi;
    }
    __syncthreads();

    // degrad -> A_hi slot only (f16)
    #pragma unroll
    for (int j2 = 0; j2 < 16; j2++){
        int dcol = j2*8 + 2*tig;
        int rl_lo = w*16 + gid, rl_hi = rl_lo + 8;
        *(uint32_t*)(smem + rl_lo*272 + dcol*2) = pack_h2(acc2[j2][0]*inv_lo, acc2[j2][1]*inv_lo);
        *(uint32_t*)(smem + rl_hi*272 + dcol*2) = pack_h2(acc2[j2][2]*inv_hi, acc2[j2][3]*inv_hi);
    }

    // ===== phase 3: conv_out (1-pass: Whi x Dhi) =====
    for (int co = 0; co < 3; co++){
        __syncthreads();
        stage136(smem + 69632, g_wouthi + (size_t)(co*128)*DDIM, DDIM);
        __syncthreads();
        float acc3[16][4] = {};
        #pragma unroll
        for (int ks = 0; ks < 8; ks++){
            uint32_t ah[4];
            ldmx4(ah, aAddr(o_Bh + (uint32_t)(w*16)*272u, ks*16, lane));
            #pragma unroll
            for (int j2 = 0; j2 < 8; j2++){
                uint32_t bh[4];
                ldmx4(bh, bAddr4(o_Ah, j2*16, ks*16, lane));
                mma16816(acc3[2*j2],   ah, bh);
                mma16816(acc3[2*j2+1], ah, bh+2);
            }
        }
        int orow = co*128 + w*16 + gid;
        float bb0 = __ldg(cob + orow), bb1 = __ldg(cob + orow + 8);
        #pragma unroll
        for (int j = 0; j < 16; j++){
            int col = l0 + j*8 + 2*tig;
            *(float2*)&outp[OUT_IMG + ((size_t)(b*CIN + orow))*HWSZ + col] =
                make_float2(acc3[j][0] + bb0, acc3[j][1] + bb0);
            *(float2*)&outp[OUT_IMG + ((size_t)(b*CIN + orow + 8))*HWSZ + col] =
                make_float2(acc3[j][2] + bb1, acc3[j][3] + bb1);
        }
    }
}

// ---------------- K5: mask + top-81 via radix select ----------------
__global__ __launch_bounds__(1024) void k_topk_mask(float* __restrict__ outp){
    __shared__ uint32_t hist[256];
    __shared__ uint32_t s_prefix;
    __shared__ int s_krem;
    __shared__ float sred[32];
    __shared__ float s_mn, s_mx;
    __shared__ unsigned long long cand[256];
    __shared__ uint32_t s_cnt;
    int b = blockIdx.x, t = threadIdx.x;
    int lane = t & 31, w = t >> 5;
    float v[4];
    float mn = 1e30f, mx = -1e30f;
    #pragma unroll
    for (int i = 0; i < 4; i++){
        v[i] = g_rowmax[b*HWSZ + t + (i<<10)];
        mn = fminf(mn, v[i]); mx = fmaxf(mx, v[i]);
    }
    mn = wMinF(mn);
    if (lane == 0) sred[w] = mn;
    __syncthreads();
    if (w == 0){ float x = wMinF(sred[lane]); if (lane == 0) s_mn = x; }
    __syncthreads();
    mx = wMaxF(mx);
    if (lane == 0) sred[w] = mx;
    __syncthreads();
    if (w == 0){ float x = wMaxF(sred[lane]); if (lane == 0) s_mx = x; }
    __syncthreads();
    float mn3 = s_mn*s_mn*s_mn, mx3 = s_mx*s_mx*s_mx;
    float inv = 1.f / (mx3 - mn3);
    #pragma unroll
    for (int i = 0; i < 4; i++){
        int l = t + (i<<10);
        outp[OUT_MASK + b*HWSZ + l] = 1.f - (v[i]*v[i]*v[i] - mn3) * inv;
    }

    uint32_t kb[4];
    #pragma unroll
    for (int i = 0; i < 4; i++) kb[i] = __float_as_uint(v[i]);

    if (t == 0){ s_prefix = 0u; s_krem = KSEL; s_cnt = 0u; }

    #pragma unroll
    for (int round = 0; round < 4; round++){
        int shift = 24 - 8*round;
        uint32_t pm = (round == 0) ? 0u : (0xFFFFFFFFu << (32 - 8*round));
        if (t < 256) hist[t] = 0;
        __syncthreads();
        uint32_t P = s_prefix;
        #pragma unroll
        for (int i = 0; i < 4; i++)
            if ((kb[i] & pm) == P) atomicAdd(&hist[(kb[i] >> shift) & 255], 1);
        __syncthreads();
        if (w == 0){
            uint32_t loc[8]; uint32_t ls = 0;
            #pragma unroll
            for (int j = 0; j < 8; j++){ loc[j] = hist[lane*8 + j]; ls += loc[j]; }
            uint32_t incl = ls;
            #pragma unroll
            for (int o = 1; o < 32; o <<= 1){
                uint32_t u = __shfl_down_sync(0xFFFFFFFFu, incl, o);
                if (lane + o < 32) incl += u;
            }
            uint32_t H = incl - ls;
            int krem = s_krem;
            if ((int)H < krem && krem <= (int)incl){
                uint32_t cum = H;
                #pragma unroll
                for (int j = 7; j >= 0; j--){
                    uint32_t above = cum;
                    cum += loc[j];
                    if ((int)above < krem && krem <= (int)cum){
                        s_prefix = s_prefix | ((uint32_t)(lane*8 + j) << shift);
                        s_krem = krem - (int)above;
                        break;
                    }
                }
            }
        }
        __syncthreads();
    }

    uint32_t T = s_prefix;
    #pragma unroll
    for (int i = 0; i < 4; i++){
        if (kb[i] >= T){
            int l = t + (i<<10);
            uint32_t pos = atomicAdd(&s_cnt, 1u);
            if (pos < 256)
                cand[pos] = ((unsigned long long)kb[i] << 32) | (unsigned)(0xFFFFFFFFu - (unsigned)l);
        }
    }
    __syncthreads();
    int S = (int)s_cnt; if (S > 256) S = 256;
    if (t < S){
        unsigned long long key = cand[t];
        int rank = 0;
        for (int j = 0; j < S; j++) rank += (cand[j] > key);
        if (rank < KSEL)
            g_topidx[b*KSEL + rank] = (int)(0xFFFFFFFFu - (unsigned)(key & 0xFFFFFFFFull));
    }
}

// ---------------- K7: gather ----------------
__global__ __launch_bounds__(128) void k_gather(float* __restrict__ outp){
    int g = blockIdx.x;
    int b = g / (BTOT*KSEL);
    int rem = g - b*(BTOT*KSEL);
    int i = rem / KSEL, k = rem - i*KSEL;
    int src = g_topidx[i*KSEL + k];
    size_t row = (size_t)(b*HWSZ + src);
    float inv = g_rowinv[row];
    const float4* s = (const float4*)&g_simE[row*NTOK];
    float4* o = (float4*)&outp[OUT_RES + (size_t)g*NTOK];
    float4 vv = s[threadIdx.x];
    vv.x *= inv; vv.y *= inv; vv.z *= inv; vv.w *= inv;
    o[threadIdx.x] = vv;
}

// ---------------- launch ----------------
extern "C" void kernel_launch(void* const* d_in, const int* in_sizes, int n_in,
                              void* d_out, int out_size){
    const float* x   = (const float*)d_in[0];
    const float* DRp = (const float*)d_in[1];
    const float* ciw = (const float*)d_in[2];
    const float* cib = (const float*)d_in[3];
    const float* sw  = (const float*)d_in[4];
    const float* sb  = (const float*)d_in[5];
    const float* n1w = (const float*)d_in[6];
    const float* n1b = (const float*)d_in[7];
    const float* n2w = (const float*)d_in[8];
    const float* n2b = (const float*)d_in[9];
    const float* cow = (const float*)d_in[10];
    const float* cob = (const float*)d_in[11];
    float* out = (float*)d_out;

    cudaFuncSetAttribute(k_fused, cudaFuncAttributeMaxDynamicSharedMemorySize, SMEM_FUSED);

    k_prep_all <<<320, 384>>>(sw, ciw, cib, sb, cow, DRp, n2w, n2b);
    k_fused    <<<MROW/128, 256, SMEM_FUSED>>>(x, n1w, n1b, cob, out);
    k_topk_mask<<<BTOT, 1024>>>(out);
    k_gather   <<<BTOT*BTOT*KSEL, 128>>>(out);
}

// round 16
// speedup vs baseline: 1.1275x; 1.0169x over previous
#include <cuda_runtime.h>
#include <cuda_fp16.h>
#include <cstdint>

#define BTOT 8
#define CIN  384
#define HWSZ 4096
#define DDIM 128
#define NTOK 512
#define MROW (BTOT*HWSZ)   // 32768
#define KSEL 81
#define LN_EPS 1e-5f

#define OUT_MASK 0
#define OUT_IMG  32768
#define OUT_RES  (32768 + BTOT*CIN*HWSZ)

// ---------------- scratch ----------------
__device__ __half g_W2hi[DDIM*CIN];
__device__ __half g_W2lo[DDIM*CIN];
__device__ float g_b2[DDIM];
__device__ __half g_wouthi[CIN*DDIM];
__device__ __half g_dr_hi[NTOK*DDIM];
__device__ __half g_dr_lo[NTOK*DDIM];
__device__ float g_rn[NTOK];
__device__ __half g_simEh[(size_t)MROW*NTOK];   // unnormalized exp(sim), fp16
__device__ float g_rowinv[MROW];
__device__ float g_rowmax[MROW];
__device__ int   g_topidx[BTOT*KSEL];

// ---------------- helpers ----------------
__device__ __forceinline__ uint32_t smem_u32(const void* p){
    uint32_t a; asm("{ .reg .u64 t; cvta.to.shared.u64 t, %1; cvt.u32.u64 %0, t; }" : "=r"(a) : "l"(p));
    return a;
}
__device__ __forceinline__ void ldmx4(uint32_t* r, uint32_t addr){
    asm volatile("ldmatrix.sync.aligned.m8n8.x4.shared.b16 {%0,%1,%2,%3}, [%4];"
        : "=r"(r[0]),"=r"(r[1]),"=r"(r[2]),"=r"(r[3]) : "r"(addr));
}
__device__ __forceinline__ void ldmx4t(uint32_t* r, uint32_t addr){
    asm volatile("ldmatrix.sync.aligned.m8n8.x4.trans.shared.b16 {%0,%1,%2,%3}, [%4];"
        : "=r"(r[0]),"=r"(r[1]),"=r"(r[2]),"=r"(r[3]) : "r"(addr));
}
__device__ __forceinline__ void mma16816(float* c, const uint32_t* a, const uint32_t* b){
    asm volatile("mma.sync.aligned.m16n8k16.row.col.f32.f16.f16.f32 "
        "{%0,%1,%2,%3},{%4,%5,%6,%7},{%8,%9},{%0,%1,%2,%3};"
        : "+f"(c[0]),"+f"(c[1]),"+f"(c[2]),"+f"(c[3])
        : "r"(a[0]),"r"(a[1]),"r"(a[2]),"r"(a[3]),"r"(b[0]),"r"(b[1]));
}
__device__ __forceinline__ uint32_t pack_h2(float a, float b){
    __half2 t = __floats2half2_rn(a,b);
    return *(uint32_t*)&t;
}
// stage 128x128 f16 tile to smem (272B pitch) -- 256 threads
__device__ __forceinline__ void stage136(char* dst, const __half* __restrict__ src, int stride){
    int t = threadIdx.x;
    #pragma unroll
    for (int i = 0; i < 8; i++){
        int idx = t + (i<<8);
        int row = idx >> 4, c8 = (idx & 15) << 3;
        *(uint4*)(dst + row*272 + c8*2) = *(const uint4*)(src + (size_t)row*stride + c8);
    }
}
__device__ __forceinline__ uint32_t aAddr(uint32_t tileBase, int k0, int lane){
    return tileBase + (uint32_t)(lane & 15)*272u + (uint32_t)(k0 + ((lane>>4)<<3))*2u;
}
__device__ __forceinline__ uint32_t aTAddr(uint32_t base, int m0, int k0, int lane){
    int row = k0 + ((lane>>4)<<3) + (lane&7);
    int col = m0 + (((lane>>3)&1)<<3);
    return base + (uint32_t)row*272u + (uint32_t)col*2u;
}
__device__ __forceinline__ uint32_t bAddr4(uint32_t base, int n0, int k0, int lane){
    int row = n0 + ((lane>>4)<<3) + (lane&7);
    int col = k0 + ((lane>>3)&1)*8;
    return base + (uint32_t)row*272u + (uint32_t)col*2u;
}
__device__ __forceinline__ uint32_t bTAddr4(uint32_t base, int n0, int k0, int lane){
    int row = k0 + ((lane>>3)&1)*8 + (lane&7);
    int col = n0 + ((lane>>4)<<3);
    return base + (uint32_t)row*272u + (uint32_t)col*2u;
}
__device__ __forceinline__ float wSum(float v){
    #pragma unroll
    for (int o=16;o;o>>=1) v += __shfl_xor_sync(0xFFFFFFFFu, v, o);
    return v;
}
__device__ __forceinline__ float wMaxF(float v){
    #pragma unroll
    for (int o=16;o;o>>=1) v = fmaxf(v, __shfl_xor_sync(0xFFFFFFFFu, v, o));
    return v;
}
__device__ __forceinline__ float wMinF(float v){
    #pragma unroll
    for (int o=16;o;o>>=1) v = fminf(v, __shfl_xor_sync(0xFFFFFFFFu, v, o));
    return v;
}
__device__ __forceinline__ float qSum(float v){
    v += __shfl_xor_sync(0xFFFFFFFFu, v, 1);
    v += __shfl_xor_sync(0xFFFFFFFFu, v, 2);
    return v;
}
__device__ __forceinline__ float qMax(float v){
    v = fmaxf(v, __shfl_xor_sync(0xFFFFFFFFu, v, 1));
    v = fmaxf(v, __shfl_xor_sync(0xFFFFFFFFu, v, 2));
    return v;
}

// ---------------- K0: merged prep (W2, wout, DR layernorm) ----------------
__global__ __launch_bounds__(384) void k_prep_all(const float* __restrict__ sw,
                                                  const float* __restrict__ ciw,
                                                  const float* __restrict__ cib,
                                                  const float* __restrict__ semb,
                                                  const float* __restrict__ cow,
                                                  const float* __restrict__ DRp,
                                                  const float* __restrict__ n2w,
                                                  const float* __restrict__ n2b){
    int bid = blockIdx.x, t = threadIdx.x;
    if (bid < 128){
        __shared__ float srow[128];
        int o = bid;
        if (t < 128) srow[t] = sw[o*DDIM + t];
        __syncthreads();
        float acc = 0.f;
        #pragma unroll 4
        for (int d = 0; d < 128; d++) acc += srow[d] * ciw[d*CIN + t];
        __half h = __float2half(acc);
        g_W2hi[o*CIN + t] = h;
        g_W2lo[o*CIN + t] = __float2half(acc - __half2float(h));
        if (t == 0){
            float bacc = 0.f;
            for (int d = 0; d < 128; d++) bacc += srow[d] * cib[d];
            g_b2[o] = bacc + semb[o];
        }
    } else if (bid < 256){
        int id = (bid - 128)*384 + t;
        g_wouthi[id] = __float2half(cow[id]);
    } else {
        int w = t >> 5, lane = t & 31;
        if (w < 8){
            int n = (bid - 256)*8 + w;
            float v[4];
            float s = 0.f;
            #pragma unroll
            for (int i = 0; i < 4; i++){ v[i] = DRp[n*DDIM + lane + (i<<5)]; s += v[i]; }
            float mean = wSum(s) * (1.f/DDIM);
            float q = 0.f;
            #pragma unroll
            for (int i = 0; i < 4; i++){ float d = v[i]-mean; q += d*d; }
            float rstd = rsqrtf(wSum(q)*(1.f/DDIM) + LN_EPS);
            float ln[4]; float ss = 0.f;
            #pragma unroll
            for (int i = 0; i < 4; i++){
                int dd = lane + (i<<5);
                ln[i] = (v[i]-mean)*rstd*n2w[dd] + n2b[dd];
                ss += ln[i]*ln[i];
            }
            ss = wSum(ss);
            #pragma unroll
            for (int i = 0; i < 4; i++){
                int dd = lane + (i<<5);
                __half h = __float2half(ln[i]);
                g_dr_hi[n*DDIM + dd] = h;
                g_dr_lo[n*DDIM + dd] = __float2half(ln[i] - __half2float(h));
            }
            if (lane == 0) g_rn[n] = rsqrtf(ss);
        }
    }
}

// ========== K2: FUSED sem(3p) + double-LN + sim(3p) + softmax + degrad(1p) + conv_out(1p) ==========
#define SMEM_FUSED (139264 + 3584)
__global__ __launch_bounds__(256,1) void k_fused(const float* __restrict__ x,
                                                 const float* __restrict__ n1w,
                                                 const float* __restrict__ n1b,
                                                 const float* __restrict__ cob,
                                                 float* __restrict__ outp){
    extern __shared__ char smem[];
    uint32_t sb = smem_u32(smem);
    int t = threadIdx.x, lane = t & 31, w = t >> 5;
    int m0 = blockIdx.x * 128;
    int b = m0 >> 12, l0 = m0 & 4095;

    uint32_t o_Ah = sb, o_Al = sb + 34816;
    uint32_t o_Bh = sb + 69632, o_Bl = sb + 104448;
    float* W1v = (float*)(smem + 139264);
    float* B1v = W1v + 128;
    float* b2v = B1v + 128;
    float* rnv = b2v + 128;
    if (t < 128){ W1v[t] = n1w[t]; B1v[t] = n1b[t]; b2v[t] = g_b2[t]; }
    rnv[t] = g_rn[t]; rnv[t+256] = g_rn[t+256];

    const float* xb = x + (size_t)b * CIN * HWSZ + l0;
    float acc[16][4] = {};

    // ===== phase 1: GEMM1, K=384 (3-pass) =====
    for (int ch = 0; ch < 3; ch++){
        if (ch) __syncthreads();
        #pragma unroll
        for (int i = 0; i < 16; i++){
            int id = t + (i<<8);
            int cr = id >> 5;
            int lq = (id & 31) << 2;
            float4 vv = *(const float4*)(xb + (size_t)(ch*128 + cr)*HWSZ + lq);
            float hx = __half2float(__float2half(vv.x));
            float hy = __half2float(__float2half(vv.y));
            float hz = __half2float(__float2half(vv.z));
            float hw = __half2float(__float2half(vv.w));
            *(uint2*)(smem + cr*272 + lq*2) = make_uint2(pack_h2(vv.x, vv.y), pack_h2(vv.z, vv.w));
            *(uint2*)(smem + 34816 + cr*272 + lq*2) = make_uint2(pack_h2(vv.x-hx, vv.y-hy), pack_h2(vv.z-hz, vv.w-hw));
        }
        #pragma unroll
        for (int i = 0; i < 8; i++){
            int idx = t + (i<<8);
            int row = idx >> 4, c8 = (idx & 15) << 3;
            *(uint4*)(smem + 69632  + row*272 + c8*2) = *(const uint4*)(g_W2hi + row*CIN + ch*128 + c8);
            *(uint4*)(smem + 104448 + row*272 + c8*2) = *(const uint4*)(g_W2lo + row*CIN + ch*128 + c8);
        }
        __syncthreads();
        #pragma unroll
        for (int ks = 0; ks < 8; ks++){
            uint32_t ah[4], al[4];
            ldmx4t(ah, aTAddr(o_Ah, w*16, ks*16, lane));
            ldmx4t(al, aTAddr(o_Al, w*16, ks*16, lane));
            #pragma unroll
            for (int j2 = 0; j2 < 8; j2++){
                uint32_t bh[4], bl[4];
                ldmx4(bh, bAddr4(o_Bh, j2*16, ks*16, lane));
                ldmx4(bl, bAddr4(o_Bl, j2*16, ks*16, lane));
                mma16816(acc[2*j2],   ah, bh);
                mma16816(acc[2*j2+1], ah, bh+2);
                mma16816(acc[2*j2],   ah, bl);
                mma16816(acc[2*j2+1], ah, bl+2);
                mma16816(acc[2*j2],   al, bh);
                mma16816(acc[2*j2+1], al, bh+2);
            }
        }
    }
    __syncthreads();

    // ===== double-LN epilogue -> A tile (ln2*cdlinv, f16 hi/lo) =====
    int gid = lane >> 2, tig = lane & 3;
    #pragma unroll
    for (int half = 0; half < 2; half++){
        int rl = w*16 + gid + half*8;
        float v[32];
        #pragma unroll
        for (int j = 0; j < 16; j++){
            int col = j*8 + 2*tig;
            v[2*j]   = acc[j][2*half]   + b2v[col];
            v[2*j+1] = acc[j][2*half+1] + b2v[col+1];
        }
        float s = 0.f;
        #pragma unroll
        for (int k = 0; k < 32; k++) s += v[k];
        float mean = qSum(s) * (1.f/DDIM);
        float q = 0.f;
        #pragma unroll
        for (int k = 0; k < 32; k++){ float d = v[k]-mean; q += d*d; }
        float rstd = rsqrtf(qSum(q)*(1.f/DDIM) + LN_EPS);
        float ln1[32]; float ss = 0.f, s2 = 0.f;
        #pragma unroll
        for (int j = 0; j < 16; j++){
            int col = j*8 + 2*tig;
            #pragma unroll
            for (int u = 0; u < 2; u++){
                float y = (v[2*j+u]-mean)*rstd*W1v[col+u] + B1v[col+u];
                ln1[2*j+u] = y; ss += y*y; s2 += y;
            }
        }
        float cdlinv = rsqrtf(qSum(ss));
        float m2 = qSum(s2) * (1.f/DDIM);
        float q2 = 0.f;
        #pragma unroll
        for (int k = 0; k < 32; k++){ float d = ln1[k]-m2; q2 += d*d; }
        float rstd2 = rsqrtf(qSum(q2)*(1.f/DDIM) + LN_EPS);
        #pragma unroll
        for (int j = 0; j < 16; j++){
            int col = j*8 + 2*tig;
            float y0 = ((ln1[2*j]-m2)*rstd2*W1v[col] + B1v[col]) * cdlinv;
            float y1 = ((ln1[2*j+1]-m2)*rstd2*W1v[col+1] + B1v[col+1]) * cdlinv;
            float h0 = __half2float(__float2half(y0));
            float h1 = __half2float(__float2half(y1));
            *(uint32_t*)(smem + rl*272 + col*2) = pack_h2(y0, y1);
            *(uint32_t*)(smem + 34816 + rl*272 + col*2) = pack_h2(y0-h0, y1-h1);
        }
    }

    // ===== phase 2: sim (3-pass) + softmax + degrad (1-pass) =====
    uint32_t aTh = o_Ah + (uint32_t)(w*16)*272u;
    uint32_t aTl = o_Al + (uint32_t)(w*16)*272u;
    int rlo = m0 + w*16 + gid, rhi = rlo + 8;

    float acc2[16][4] = {};
    float sum_lo = 0.f, sum_hi = 0.f, emax_lo = 0.f, emax_hi = 0.f;

    for (int c = 0; c < 4; c++){
        __syncthreads();
        stage136(smem + 69632,  g_dr_hi + (size_t)c*128*DDIM, DDIM);
        stage136(smem + 104448, g_dr_lo + (size_t)c*128*DDIM, DDIM);
        __syncthreads();

        float acc1[16][4] = {};
        #pragma unroll
        for (int ks = 0; ks < 8; ks++){
            uint32_t ah[4], al[4];
            ldmx4(ah, aAddr(aTh, ks*16, lane));
            ldmx4(al, aAddr(aTl, ks*16, lane));
            #pragma unroll
            for (int j2 = 0; j2 < 8; j2++){
                uint32_t bh[4], bl[4];
                ldmx4(bh, bAddr4(o_Bh, j2*16, ks*16, lane));
                ldmx4(bl, bAddr4(o_Bl, j2*16, ks*16, lane));
                mma16816(acc1[2*j2],   ah, bh);
                mma16816(acc1[2*j2+1], ah, bh+2);
                mma16816(acc1[2*j2],   ah, bl);
                mma16816(acc1[2*j2+1], ah, bl+2);
                mma16816(acc1[2*j2],   al, bh);
                mma16816(acc1[2*j2+1], al, bh+2);
            }
        }

        uint32_t ehi[16][2];
        #pragma unroll
        for (int j = 0; j < 16; j++){
            int coll = j*8 + 2*tig;
            float rn0 = rnv[c*128 + coll], rn1 = rnv[c*128 + coll + 1];
            float e0 = __expf(acc1[j][0]*rn0), e1 = __expf(acc1[j][1]*rn1);
            float e2 = __expf(acc1[j][2]*rn0), e3 = __expf(acc1[j][3]*rn1);
            sum_lo += e0 + e1; sum_hi += e2 + e3;
            emax_lo = fmaxf(emax_lo, fmaxf(e0, e1));
            emax_hi = fmaxf(emax_hi, fmaxf(e2, e3));
            int col = c*128 + coll;
            uint32_t p0 = pack_h2(e0, e1), p1 = pack_h2(e2, e3);
            *(uint32_t*)&g_simEh[(size_t)rlo*NTOK + col] = p0;
            *(uint32_t*)&g_simEh[(size_t)rhi*NTOK + col] = p1;
            ehi[j][0] = p0;
            ehi[j][1] = p1;
        }

        // degrad: 1-pass (P_hi x dr_hi)
        #pragma unroll
        for (int k = 0; k < 8; k++){
            uint32_t ah[4] = { ehi[2*k][0], ehi[2*k][1], ehi[2*k+1][0], ehi[2*k+1][1] };
            #pragma unroll
            for (int j4 = 0; j4 < 8; j4++){
                uint32_t bh[4];
                ldmx4t(bh, bTAddr4(o_Bh, j4*16, k*16, lane));
                mma16816(acc2[2*j4],   ah, bh);
                mma16816(acc2[2*j4+1], ah, bh+2);
            }
        }
    }

    sum_lo = qSum(sum_lo); sum_hi = qSum(sum_hi);
    emax_lo = qMax(emax_lo); emax_hi = qMax(emax_hi);
    float inv_lo = 1.f / sum_lo, inv_hi = 1.f / sum_hi;
    if (tig == 0){
        g_rowinv[rlo] = inv_lo;  g_rowinv[rhi] = inv_hi;
        g_rowmax[rlo] = emax_lo * inv_lo;  g_rowmax[rhi] = emax_hi * inv_hi;
    }
    __syncthreads();

    // degrad -> A_hi slot only (f16)
    #pragma unroll
    for (int j2 = 0; j2 < 16; j2++){
        int dcol = j2*8 + 2*tig;
        int rl_lo = w*16 + gid, rl_hi = rl_lo + 8;
        *(uint32_t*)(smem + rl_lo*272 + dcol*2) = pack_h2(acc2[j2][0]*inv_lo, acc2[j2][1]*inv_lo);
        *(uint32_t*)(smem + rl_hi*272 + dcol*2) = pack_h2(acc2[j2][2]*inv_hi, acc2[j2][3]*inv_hi);
    }

    // ===== phase 3: conv_out (1-pass: Whi x Dhi) =====
    for (int co = 0; co < 3; co++){
        __syncthreads();
        stage136(smem + 69632, g_wouthi + (size_t)(co*128)*DDIM, DDIM);
        __syncthreads();
        float acc3[16][4] = {};
        #pragma unroll
        for (int ks = 0; ks < 8; ks++){
            uint32_t ah[4];
            ldmx4(ah, aAddr(o_Bh + (uint32_t)(w*16)*272u, ks*16, lane));
            #pragma unroll
            for (int j2 = 0; j2 < 8; j2++){
                uint32_t bh[4];
                ldmx4(bh, bAddr4(o_Ah, j2*16, ks*16, lane));
                mma16816(acc3[2*j2],   ah, bh);
                mma16816(acc3[2*j2+1], ah, bh+2);
            }
        }
        int orow = co*128 + w*16 + gid;
        float bb0 = __ldg(cob + orow), bb1 = __ldg(cob + orow + 8);
        #pragma unroll
        for (int j = 0; j < 16; j++){
            int col = l0 + j*8 + 2*tig;
            *(float2*)&outp[OUT_IMG + ((size_t)(b*CIN + orow))*HWSZ + col] =
                make_float2(acc3[j][0] + bb0, acc3[j][1] + bb0);
            *(float2*)&outp[OUT_IMG + ((size_t)(b*CIN + orow + 8))*HWSZ + col] =
                make_float2(acc3[j][2] + bb1, acc3[j][3] + bb1);
        }
    }
}

// ---------------- K5: mask + top-81 via radix select ----------------
__global__ __launch_bounds__(1024) void k_topk_mask(float* __restrict__ outp){
    __shared__ uint32_t hist[256];
    __shared__ uint32_t s_prefix;
    __shared__ int s_krem;
    __shared__ float sred[32];
    __shared__ float s_mn, s_mx;
    __shared__ unsigned long long cand[256];
    __shared__ uint32_t s_cnt;
    int b = blockIdx.x, t = threadIdx.x;
    int lane = t & 31, w = t >> 5;
    float v[4];
    float mn = 1e30f, mx = -1e30f;
    #pragma unroll
    for (int i = 0; i < 4; i++){
        v[i] = g_rowmax[b*HWSZ + t + (i<<10)];
        mn = fminf(mn, v[i]); mx = fmaxf(mx, v[i]);
    }
    mn = wMinF(mn);
    if (lane == 0) sred[w] = mn;
    __syncthreads();
    if (w == 0){ float x = wMinF(sred[lane]); if (lane == 0) s_mn = x; }
    __syncthreads();
    mx = wMaxF(mx);
    if (lane == 0) sred[w] = mx;
    __syncthreads();
    if (w == 0){ float x = wMaxF(sred[lane]); if (lane == 0) s_mx = x; }
    __syncthreads();
    float mn3 = s_mn*s_mn*s_mn, mx3 = s_mx*s_mx*s_mx;
    float inv = 1.f / (mx3 - mn3);
    #pragma unroll
    for (int i = 0; i < 4; i++){
        int l = t + (i<<10);
        outp[OUT_MASK + b*HWSZ + l] = 1.f - (v[i]*v[i]*v[i] - mn3) * inv;
    }

    uint32_t kb[4];
    #pragma unroll
    for (int i = 0; i < 4; i++) kb[i] = __float_as_uint(v[i]);

    if (t == 0){ s_prefix = 0u; s_krem = KSEL; s_cnt = 0u; }

    #pragma unroll
    for (int round = 0; round < 4; round++){
        int shift = 24 - 8*round;
        uint32_t pm = (round == 0) ? 0u : (0xFFFFFFFFu << (32 - 8*round));
        if (t < 256) hist[t] = 0;
        __syncthreads();
        uint32_t P = s_prefix;
        #pragma unroll
        for (int i = 0; i < 4; i++)
            if ((kb[i] & pm) == P) atomicAdd(&hist[(kb[i] >> shift) & 255], 1);
        __syncthreads();
        if (w == 0){
            uint32_t loc[8]; uint32_t ls = 0;
            #pragma unroll
            for (int j = 0; j < 8; j++){ loc[j] = hist[lane*8 + j]; ls += loc[j]; }
            uint32_t incl = ls;
            #pragma unroll
            for (int o = 1; o < 32; o <<= 1){
                uint32_t u = __shfl_down_sync(0xFFFFFFFFu, incl, o);
                if (lane + o < 32) incl += u;
            }
            uint32_t H = incl - ls;
            int krem = s_krem;
            if ((int)H < krem && krem <= (int)incl){
                uint32_t cum = H;
                #pragma unroll
                for (int j = 7; j >= 0; j--){
                    uint32_t above = cum;
                    cum += loc[j];
                    if ((int)above < krem && krem <= (int)cum){
                        s_prefix = s_prefix | ((uint32_t)(lane*8 + j) << shift);
                        s_krem = krem - (int)above;
                        break;
                    }
                }
            }
        }
        __syncthreads();
    }

    uint32_t T = s_prefix;
    #pragma unroll
    for (int i = 0; i < 4; i++){
        if (kb[i] >= T){
            int l = t + (i<<10);
            uint32_t pos = atomicAdd(&s_cnt, 1u);
            if (pos < 256)
                cand[pos] = ((unsigned long long)kb[i] << 32) | (unsigned)(0xFFFFFFFFu - (unsigned)l);
        }
    }
    __syncthreads();
    int S = (int)s_cnt; if (S > 256) S = 256;
    if (t < S){
        unsigned long long key = cand[t];
        int rank = 0;
        for (int j = 0; j < S; j++) rank += (cand[j] > key);
        if (rank < KSEL)
            g_topidx[b*KSEL + rank] = (int)(0xFFFFFFFFu - (unsigned)(key & 0xFFFFFFFFull));
    }
}

// ---------------- K7: gather (fp16 source) ----------------
__global__ __launch_bounds__(128) void k_gather(float* __restrict__ outp){
    int g = blockIdx.x;
    int b = g / (BTOT*KSEL);
    int rem = g - b*(BTOT*KSEL);
    int i = rem / KSEL, k = rem - i*KSEL;
    int src = g_topidx[i*KSEL + k];
    size_t row = (size_t)(b*HWSZ + src);
    float inv = g_rowinv[row];
    const uint2* s = (const uint2*)&g_simEh[row*NTOK];
    float4* o = (float4*)&outp[OUT_RES + (size_t)g*NTOK];
    uint2 pk = s[threadIdx.x];
    __half2 h0 = *(__half2*)&pk.x, h1 = *(__half2*)&pk.y;
    float2 f0 = __half22float2(h0), f1 = __half22float2(h1);
    o[threadIdx.x] = make_float4(f0.x*inv, f0.y*inv, f1.x*inv, f1.y*inv);
}

// ---------------- launch ----------------
extern "C" void kernel_launch(void* const* d_in, const int* in_sizes, int n_in,
                              void* d_out, int out_size){
    const float* x   = (const float*)d_in[0];
    const float* DRp = (const float*)d_in[1];
    const float* ciw = (const float*)d_in[2];
    const float* cib = (const float*)d_in[3];
    const float* sw  = (const float*)d_in[4];
    const float* sb  = (const float*)d_in[5];
    const float* n1w = (const float*)d_in[6];
    const float* n1b = (const float*)d_in[7];
    const float* n2w = (const float*)d_in[8];
    const float* n2b = (const float*)d_in[9];
    const float* cow = (const float*)d_in[10];
    const float* cob = (const float*)d_in[11];
    float* out = (float*)d_out;

    cudaFuncSetAttribute(k_fused, cudaFuncAttributeMaxDynamicSharedMemorySize, SMEM_FUSED);

    k_prep_all <<<320, 384>>>(sw, ciw, cib, sb, cow, DRp, n2w, n2b);
    k_fused    <<<MROW/128, 256, SMEM_FUSED>>>(x, n1w, n1b, cob, out);
    k_topk_mask<<<BTOT, 1024>>>(out);
    k_gather   <<<BTOT*BTOT*KSEL, 128>>>(out);
}

// round 17
// speedup vs baseline: 1.1360x; 1.0075x over previous
#include <cuda_runtime.h>
#include <cuda_fp16.h>
#include <cstdint>

#define BTOT 8
#define CIN  384
#define HWSZ 4096
#define DDIM 128
#define NTOK 512
#define MROW (BTOT*HWSZ)   // 32768
#define KSEL 81
#define LN_EPS 1e-5f

#define OUT_MASK 0
#define OUT_IMG  32768
#define OUT_RES  (32768 + BTOT*CIN*HWSZ)

// ---------------- scratch ----------------
__device__ __half g_W2hi[DDIM*CIN];
__device__ __half g_W2lo[DDIM*CIN];
__device__ float g_b2[DDIM];
__device__ __half g_wouthi[CIN*DDIM];
__device__ __half g_dr_hi[NTOK*DDIM];
__device__ __half g_dr_lo[NTOK*DDIM];
__device__ float g_rn[NTOK];
__device__ __half g_simEh[(size_t)MROW*NTOK];   // unnormalized exp(sim), fp16
__device__ float g_rowinv[MROW];
__device__ float g_rowmax[MROW];
__device__ int   g_topidx[BTOT*KSEL];

// ---------------- helpers ----------------
__device__ __forceinline__ uint32_t smem_u32(const void* p){
    uint32_t a; asm("{ .reg .u64 t; cvta.to.shared.u64 t, %1; cvt.u32.u64 %0, t; }" : "=r"(a) : "l"(p));
    return a;
}
__device__ __forceinline__ void ldmx4(uint32_t* r, uint32_t addr){
    asm volatile("ldmatrix.sync.aligned.m8n8.x4.shared.b16 {%0,%1,%2,%3}, [%4];"
        : "=r"(r[0]),"=r"(r[1]),"=r"(r[2]),"=r"(r[3]) : "r"(addr));
}
__device__ __forceinline__ void ldmx4t(uint32_t* r, uint32_t addr){
    asm volatile("ldmatrix.sync.aligned.m8n8.x4.trans.shared.b16 {%0,%1,%2,%3}, [%4];"
        : "=r"(r[0]),"=r"(r[1]),"=r"(r[2]),"=r"(r[3]) : "r"(addr));
}
__device__ __forceinline__ void mma16816(float* c, const uint32_t* a, const uint32_t* b){
    asm volatile("mma.sync.aligned.m16n8k16.row.col.f32.f16.f16.f32 "
        "{%0,%1,%2,%3},{%4,%5,%6,%7},{%8,%9},{%0,%1,%2,%3};"
        : "+f"(c[0]),"+f"(c[1]),"+f"(c[2]),"+f"(c[3])
        : "r"(a[0]),"r"(a[1]),"r"(a[2]),"r"(a[3]),"r"(b[0]),"r"(b[1]));
}
__device__ __forceinline__ uint32_t pack_h2(float a, float b){
    __half2 t = __floats2half2_rn(a,b);
    return *(uint32_t*)&t;
}
// stage 128x128 f16 tile to smem (272B pitch) -- 256 threads
__device__ __forceinline__ void stage136(char* dst, const __half* __restrict__ src, int stride){
    int t = threadIdx.x;
    #pragma unroll
    for (int i = 0; i < 8; i++){
        int idx = t + (i<<8);
        int row = idx >> 4, c8 = (idx & 15) << 3;
        *(uint4*)(dst + row*272 + c8*2) = *(const uint4*)(src + (size_t)row*stride + c8);
    }
}
__device__ __forceinline__ uint32_t aAddr(uint32_t tileBase, int k0, int lane){
    return tileBase + (uint32_t)(lane & 15)*272u + (uint32_t)(k0 + ((lane>>4)<<3))*2u;
}
__device__ __forceinline__ uint32_t aTAddr(uint32_t base, int m0, int k0, int lane){
    int row = k0 + ((lane>>4)<<3) + (lane&7);
    int col = m0 + (((lane>>3)&1)<<3);
    return base + (uint32_t)row*272u + (uint32_t)col*2u;
}
__device__ __forceinline__ uint32_t bAddr4(uint32_t base, int n0, int k0, int lane){
    int row = n0 + ((lane>>4)<<3) + (lane&7);
    int col = k0 + ((lane>>3)&1)*8;
    return base + (uint32_t)row*272u + (uint32_t)col*2u;
}
__device__ __forceinline__ uint32_t bTAddr4(uint32_t base, int n0, int k0, int lane){
    int row = k0 + ((lane>>3)&1)*8 + (lane&7);
    int col = n0 + ((lane>>4)<<3);
    return base + (uint32_t)row*272u + (uint32_t)col*2u;
}
__device__ __forceinline__ float wSum(float v){
    #pragma unroll
    for (int o=16;o;o>>=1) v += __shfl_xor_sync(0xFFFFFFFFu, v, o);
    return v;
}
__device__ __forceinline__ float wMaxF(float v){
    #pragma unroll
    for (int o=16;o;o>>=1) v = fmaxf(v, __shfl_xor_sync(0xFFFFFFFFu, v, o));
    return v;
}
__device__ __forceinline__ float wMinF(float v){
    #pragma unroll
    for (int o=16;o;o>>=1) v = fminf(v, __shfl_xor_sync(0xFFFFFFFFu, v, o));
    return v;
}
__device__ __forceinline__ float qSum(float v){
    v += __shfl_xor_sync(0xFFFFFFFFu, v, 1);
    v += __shfl_xor_sync(0xFFFFFFFFu, v, 2);
    return v;
}
__device__ __forceinline__ float qMax(float v){
    v = fmaxf(v, __shfl_xor_sync(0xFFFFFFFFu, v, 1));
    v = fmaxf(v, __shfl_xor_sync(0xFFFFFFFFu, v, 2));
    return v;
}

// ---------------- K0: merged prep (W2, wout, DR layernorm) ----------------
__global__ __launch_bounds__(384) void k_prep_all(const float* __restrict__ sw,
                                                  const float* __restrict__ ciw,
                                                  const float* __restrict__ cib,
                                                  const float* __restrict__ semb,
                                                  const float* __restrict__ cow,
                                                  const float* __restrict__ DRp,
                                                  const float* __restrict__ n2w,
                                                  const float* __restrict__ n2b){
    int bid = blockIdx.x, t = threadIdx.x;
    if (bid < 128){
        __shared__ float srow[128];
        int o = bid;
        if (t < 128) srow[t] = sw[o*DDIM + t];
        __syncthreads();
        float acc = 0.f;
        #pragma unroll 4
        for (int d = 0; d < 128; d++) acc += srow[d] * ciw[d*CIN + t];
        __half h = __float2half(acc);
        g_W2hi[o*CIN + t] = h;
        g_W2lo[o*CIN + t] = __float2half(acc - __half2float(h));
        if (t == 0){
            float bacc = 0.f;
            for (int d = 0; d < 128; d++) bacc += srow[d] * cib[d];
            g_b2[o] = bacc + semb[o];
        }
    } else if (bid < 256){
        int id = (bid - 128)*384 + t;
        g_wouthi[id] = __float2half(cow[id]);
    } else {
        int w = t >> 5, lane = t & 31;
        if (w < 8){
            int n = (bid - 256)*8 + w;
            float v[4];
            float s = 0.f;
            #pragma unroll
            for (int i = 0; i < 4; i++){ v[i] = DRp[n*DDIM + lane + (i<<5)]; s += v[i]; }
            float mean = wSum(s) * (1.f/DDIM);
            float q = 0.f;
            #pragma unroll
            for (int i = 0; i < 4; i++){ float d = v[i]-mean; q += d*d; }
            float rstd = rsqrtf(wSum(q)*(1.f/DDIM) + LN_EPS);
            float ln[4]; float ss = 0.f;
            #pragma unroll
            for (int i = 0; i < 4; i++){
                int dd = lane + (i<<5);
                ln[i] = (v[i]-mean)*rstd*n2w[dd] + n2b[dd];
                ss += ln[i]*ln[i];
            }
            ss = wSum(ss);
            #pragma unroll
            for (int i = 0; i < 4; i++){
                int dd = lane + (i<<5);
                __half h = __float2half(ln[i]);
                g_dr_hi[n*DDIM + dd] = h;
                g_dr_lo[n*DDIM + dd] = __float2half(ln[i] - __half2float(h));
            }
            if (lane == 0) g_rn[n] = rsqrtf(ss);
        }
    }
}

// ========== K2: FUSED sem(3p) + double-LN + sim(3p) + softmax + degrad(1p) + conv_out(1p) ==========
#define SMEM_FUSED (139264 + 3584)
__global__ __launch_bounds__(256,1) void k_fused(const float* __restrict__ x,
                                                 const float* __restrict__ n1w,
                                                 const float* __restrict__ n1b,
                                                 const float* __restrict__ cob,
                                                 float* __restrict__ outp){
    extern __shared__ char smem[];
    uint32_t sb = smem_u32(smem);
    int t = threadIdx.x, lane = t & 31, w = t >> 5;
    int m0 = blockIdx.x * 128;
    int b = m0 >> 12, l0 = m0 & 4095;

    uint32_t o_Ah = sb, o_Al = sb + 34816;
    uint32_t o_Bh = sb + 69632, o_Bl = sb + 104448;
    float* W1v = (float*)(smem + 139264);
    float* B1v = W1v + 128;
    float* b2v = B1v + 128;
    float* rnv = b2v + 128;
    if (t < 128){ W1v[t] = n1w[t]; B1v[t] = n1b[t]; b2v[t] = g_b2[t]; }
    rnv[t] = g_rn[t]; rnv[t+256] = g_rn[t+256];

    const float* xb = x + (size_t)b * CIN * HWSZ + l0;
    float acc[16][4] = {};

    // ===== phase 1: GEMM1, K=384 (3-pass) =====
    for (int ch = 0; ch < 3; ch++){
        if (ch) __syncthreads();
        #pragma unroll
        for (int i = 0; i < 16; i++){
            int id = t + (i<<8);
            int cr = id >> 5;
            int lq = (id & 31) << 2;
            float4 vv = *(const float4*)(xb + (size_t)(ch*128 + cr)*HWSZ + lq);
            float hx = __half2float(__float2half(vv.x));
            float hy = __half2float(__float2half(vv.y));
            float hz = __half2float(__float2half(vv.z));
            float hw = __half2float(__float2half(vv.w));
            *(uint2*)(smem + cr*272 + lq*2) = make_uint2(pack_h2(vv.x, vv.y), pack_h2(vv.z, vv.w));
            *(uint2*)(smem + 34816 + cr*272 + lq*2) = make_uint2(pack_h2(vv.x-hx, vv.y-hy), pack_h2(vv.z-hz, vv.w-hw));
        }
        #pragma unroll
        for (int i = 0; i < 8; i++){
            int idx = t + (i<<8);
            int row = idx >> 4, c8 = (idx & 15) << 3;
            *(uint4*)(smem + 69632  + row*272 + c8*2) = *(const uint4*)(g_W2hi + row*CIN + ch*128 + c8);
            *(uint4*)(smem + 104448 + row*272 + c8*2) = *(const uint4*)(g_W2lo + row*CIN + ch*128 + c8);
        }
        __syncthreads();
        #pragma unroll
        for (int ks = 0; ks < 8; ks++){
            uint32_t ah[4], al[4];
            ldmx4t(ah, aTAddr(o_Ah, w*16, ks*16, lane));
            ldmx4t(al, aTAddr(o_Al, w*16, ks*16, lane));
            #pragma unroll
            for (int j2 = 0; j2 < 8; j2++){
                uint32_t bh[4], bl[4];
                ldmx4(bh, bAddr4(o_Bh, j2*16, ks*16, lane));
                ldmx4(bl, bAddr4(o_Bl, j2*16, ks*16, lane));
                mma16816(acc[2*j2],   ah, bh);
                mma16816(acc[2*j2+1], ah, bh+2);
                mma16816(acc[2*j2],   ah, bl);
                mma16816(acc[2*j2+1], ah, bl+2);
                mma16816(acc[2*j2],   al, bh);
                mma16816(acc[2*j2+1], al, bh+2);
            }
        }
    }
    __syncthreads();

    // ===== double-LN epilogue -> A tile (ln2*cdlinv, f16 hi/lo) =====
    int gid = lane >> 2, tig = lane & 3;
    #pragma unroll
    for (int half = 0; half < 2; half++){
        int rl = w*16 + gid + half*8;
        float v[32];
        #pragma unroll
        for (int j = 0; j < 16; j++){
            int col = j*8 + 2*tig;
            v[2*j]   = acc[j][2*half]   + b2v[col];
            v[2*j+1] = acc[j][2*half+1] + b2v[col+1];
        }
        float s = 0.f;
        #pragma unroll
        for (int k = 0; k < 32; k++) s += v[k];
        float mean = qSum(s) * (1.f/DDIM);
        float q = 0.f;
        #pragma unroll
        for (int k = 0; k < 32; k++){ float d = v[k]-mean; q += d*d; }
        float rstd = rsqrtf(qSum(q)*(1.f/DDIM) + LN_EPS);
        float ln1[32]; float ss = 0.f, s2 = 0.f;
        #pragma unroll
        for (int j = 0; j < 16; j++){
            int col = j*8 + 2*tig;
            #pragma unroll
            for (int u = 0; u < 2; u++){
                float y = (v[2*j+u]-mean)*rstd*W1v[col+u] + B1v[col+u];
                ln1[2*j+u] = y; ss += y*y; s2 += y;
            }
        }
        float cdlinv = rsqrtf(qSum(ss));
        float m2 = qSum(s2) * (1.f/DDIM);
        float q2 = 0.f;
        #pragma unroll
        for (int k = 0; k < 32; k++){ float d = ln1[k]-m2; q2 += d*d; }
        float rstd2 = rsqrtf(qSum(q2)*(1.f/DDIM) + LN_EPS);
        #pragma unroll
        for (int j = 0; j < 16; j++){
            int col = j*8 + 2*tig;
            float y0 = ((ln1[2*j]-m2)*rstd2*W1v[col] + B1v[col]) * cdlinv;
            float y1 = ((ln1[2*j+1]-m2)*rstd2*W1v[col+1] + B1v[col+1]) * cdlinv;
            float h0 = __half2float(__float2half(y0));
            float h1 = __half2float(__float2half(y1));
            *(uint32_t*)(smem + rl*272 + col*2) = pack_h2(y0, y1);
            *(uint32_t*)(smem + 34816 + rl*272 + col*2) = pack_h2(y0-h0, y1-h1);
        }
    }

    // ===== phase 2: sim (3-pass) + softmax + degrad (1-pass) =====
    uint32_t aTh = o_Ah + (uint32_t)(w*16)*272u;
    uint32_t aTl = o_Al + (uint32_t)(w*16)*272u;
    int rlo = m0 + w*16 + gid, rhi = rlo + 8;

    float acc2[16][4] = {};
    float sum_lo = 0.f, sum_hi = 0.f, emax_lo = 0.f, emax_hi = 0.f;

    for (int c = 0; c < 4; c++){
        __syncthreads();
        stage136(smem + 69632,  g_dr_hi + (size_t)c*128*DDIM, DDIM);
        stage136(smem + 104448, g_dr_lo + (size_t)c*128*DDIM, DDIM);
        __syncthreads();

        float acc1[16][4] = {};
        #pragma unroll
        for (int ks = 0; ks < 8; ks++){
            uint32_t ah[4], al[4];
            ldmx4(ah, aAddr(aTh, ks*16, lane));
            ldmx4(al, aAddr(aTl, ks*16, lane));
            #pragma unroll
            for (int j2 = 0; j2 < 8; j2++){
                uint32_t bh[4], bl[4];
                ldmx4(bh, bAddr4(o_Bh, j2*16, ks*16, lane));
                ldmx4(bl, bAddr4(o_Bl, j2*16, ks*16, lane));
                mma16816(acc1[2*j2],   ah, bh);
                mma16816(acc1[2*j2+1], ah, bh+2);
                mma16816(acc1[2*j2],   ah, bl);
                mma16816(acc1[2*j2+1], ah, bl+2);
                mma16816(acc1[2*j2],   al, bh);
                mma16816(acc1[2*j2+1], al, bh+2);
            }
        }

        uint32_t ehi[16][2];
        #pragma unroll
        for (int j = 0; j < 16; j++){
            int coll = j*8 + 2*tig;
            float rn0 = rnv[c*128 + coll], rn1 = rnv[c*128 + coll + 1];
            float e0 = __expf(acc1[j][0]*rn0), e1 = __expf(acc1[j][1]*rn1);
            float e2 = __expf(acc1[j][2]*rn0), e3 = __expf(acc1[j][3]*rn1);
            sum_lo += e0 + e1; sum_hi += e2 + e3;
            emax_lo = fmaxf(emax_lo, fmaxf(e0, e1));
            emax_hi = fmaxf(emax_hi, fmaxf(e2, e3));
            int col = c*128 + coll;
            uint32_t p0 = pack_h2(e0, e1), p1 = pack_h2(e2, e3);
            *(uint32_t*)&g_simEh[(size_t)rlo*NTOK + col] = p0;
            *(uint32_t*)&g_simEh[(size_t)rhi*NTOK + col] = p1;
            ehi[j][0] = p0;
            ehi[j][1] = p1;
        }

        // degrad: 1-pass (P_hi x dr_hi)
        #pragma unroll
        for (int k = 0; k < 8; k++){
            uint32_t ah[4] = { ehi[2*k][0], ehi[2*k][1], ehi[2*k+1][0], ehi[2*k+1][1] };
            #pragma unroll
            for (int j4 = 0; j4 < 8; j4++){
                uint32_t bh[4];
                ldmx4t(bh, bTAddr4(o_Bh, j4*16, k*16, lane));
                mma16816(acc2[2*j4],   ah, bh);
                mma16816(acc2[2*j4+1], ah, bh+2);
            }
        }
    }

    sum_lo = qSum(sum_lo); sum_hi = qSum(sum_hi);
    emax_lo = qMax(emax_lo); emax_hi = qMax(emax_hi);
    float inv_lo = 1.f / sum_lo, inv_hi = 1.f / sum_hi;
    if (tig == 0){
        g_rowinv[rlo] = inv_lo;  g_rowinv[rhi] = inv_hi;
        g_rowmax[rlo] = emax_lo * inv_lo;  g_rowmax[rhi] = emax_hi * inv_hi;
    }
    __syncthreads();

    // degrad -> A_hi slot only (f16)
    #pragma unroll
    for (int j2 = 0; j2 < 16; j2++){
        int dcol = j2*8 + 2*tig;
        int rl_lo = w*16 + gid, rl_hi = rl_lo + 8;
        *(uint32_t*)(smem + rl_lo*272 + dcol*2) = pack_h2(acc2[j2][0]*inv_lo, acc2[j2][1]*inv_lo);
        *(uint32_t*)(smem + rl_hi*272 + dcol*2) = pack_h2(acc2[j2][2]*inv_hi, acc2[j2][3]*inv_hi);
    }

    // ===== phase 3: conv_out (1-pass: Whi x Dhi) =====
    for (int co = 0; co < 3; co++){
        __syncthreads();
        stage136(smem + 69632, g_wouthi + (size_t)(co*128)*DDIM, DDIM);
        __syncthreads();
        float acc3[16][4] = {};
        #pragma unroll
        for (int ks = 0; ks < 8; ks++){
            uint32_t ah[4];
            ldmx4(ah, aAddr(o_Bh + (uint32_t)(w*16)*272u, ks*16, lane));
            #pragma unroll
            for (int j2 = 0; j2 < 8; j2++){
                uint32_t bh[4];
                ldmx4(bh, bAddr4(o_Ah, j2*16, ks*16, lane));
                mma16816(acc3[2*j2],   ah, bh);
                mma16816(acc3[2*j2+1], ah, bh+2);
            }
        }
        int orow = co*128 + w*16 + gid;
        float bb0 = __ldg(cob + orow), bb1 = __ldg(cob + orow + 8);
        #pragma unroll
        for (int j = 0; j < 16; j++){
            int col = l0 + j*8 + 2*tig;
            *(float2*)&outp[OUT_IMG + ((size_t)(b*CIN + orow))*HWSZ + col] =
                make_float2(acc3[j][0] + bb0, acc3[j][1] + bb0);
            *(float2*)&outp[OUT_IMG + ((size_t)(b*CIN + orow + 8))*HWSZ + col] =
                make_float2(acc3[j][2] + bb1, acc3[j][3] + bb1);
        }
    }
}

// ---------------- K5: mask + top-81 via radix select ----------------
__global__ __launch_bounds__(1024) void k_topk_mask(float* __restrict__ outp){
    __shared__ uint32_t hist[256];
    __shared__ uint32_t s_prefix;
    __shared__ int s_krem;
    __shared__ float sred[32];
    __shared__ float s_mn, s_mx;
    __shared__ unsigned long long cand[256];
    __shared__ uint32_t s_cnt;
    int b = blockIdx.x, t = threadIdx.x;
    int lane = t & 31, w = t >> 5;
    float v[4];
    float mn = 1e30f, mx = -1e30f;
    #pragma unroll
    for (int i = 0; i < 4; i++){
        v[i] = g_rowmax[b*HWSZ + t + (i<<10)];
        mn = fminf(mn, v[i]); mx = fmaxf(mx, v[i]);
    }
    mn = wMinF(mn);
    if (lane == 0) sred[w] = mn;
    __syncthreads();
    if (w == 0){ float x = wMinF(sred[lane]); if (lane == 0) s_mn = x; }
    __syncthreads();
    mx = wMaxF(mx);
    if (lane == 0) sred[w] = mx;
    __syncthreads();
    if (w == 0){ float x = wMaxF(sred[lane]); if (lane == 0) s_mx = x; }
    __syncthreads();
    float mn3 = s_mn*s_mn*s_mn, mx3 = s_mx*s_mx*s_mx;
    float inv = 1.f / (mx3 - mn3);
    #pragma unroll
    for (int i = 0; i < 4; i++){
        int l = t + (i<<10);
        outp[OUT_MASK + b*HWSZ + l] = 1.f - (v[i]*v[i]*v[i] - mn3) * inv;
    }

    uint32_t kb[4];
    #pragma unroll
    for (int i = 0; i < 4; i++) kb[i] = __float_as_uint(v[i]);

    if (t == 0){ s_prefix = 0u; s_krem = KSEL; s_cnt = 0u; }

    #pragma unroll
    for (int round = 0; round < 4; round++){
        int shift = 24 - 8*round;
        uint32_t pm = (round == 0) ? 0u : (0xFFFFFFFFu << (32 - 8*round));
        if (t < 256) hist[t] = 0;
        __syncthreads();
        uint32_t P = s_prefix;
        #pragma unroll
        for (int i = 0; i < 4; i++)
            if ((kb[i] & pm) == P) atomicAdd(&hist[(kb[i] >> shift) & 255], 1);
        __syncthreads();
        if (w == 0){
            uint32_t loc[8]; uint32_t ls = 0;
            #pragma unroll
            for (int j = 0; j < 8; j++){ loc[j] = hist[lane*8 + j]; ls += loc[j]; }
            uint32_t incl = ls;
            #pragma unroll
            for (int o = 1; o < 32; o <<= 1){
                uint32_t u = __shfl_down_sync(0xFFFFFFFFu, incl, o);
                if (lane + o < 32) incl += u;
            }
            uint32_t H = incl - ls;
            int krem = s_krem;
            if ((int)H < krem && krem <= (int)incl){
                uint32_t cum = H;
                #pragma unroll
                for (int j = 7; j >= 0; j--){
                    uint32_t above = cum;
                    cum += loc[j];
                    if ((int)above < krem && krem <= (int)cum){
                        s_prefix = s_prefix | ((uint32_t)(lane*8 + j) << shift);
                        s_krem = krem - (int)above;
                        break;
                    }
                }
            }
        }
        __syncthreads();
    }

    uint32_t T = s_prefix;
    #pragma unroll
    for (int i = 0; i < 4; i++){
        if (kb[i] >= T){
            int l = t + (i<<10);
            uint32_t pos = atomicAdd(&s_cnt, 1u);
            if (pos < 256)
                cand[pos] = ((unsigned long long)kb[i] << 32) | (unsigned)(0xFFFFFFFFu - (unsigned)l);
        }
    }
    __syncthreads();
    int S = (int)s_cnt; if (S > 256) S = 256;
    if (t < S){
        unsigned long long key = cand[t];
        int rank = 0;
        for (int j = 0; j < S; j++) rank += (cand[j] > key);
        if (rank < KSEL)
            g_topidx[b*KSEL + rank] = (int)(0xFFFFFFFFu - (unsigned)(key & 0xFFFFFFFFull));
    }
}

// ---------------- K7: gather (648 blocks x 256 threads, 8 rows/block) ----------------
__global__ __launch_bounds__(256) void k_gather(float* __restrict__ outp){
    int t = threadIdx.x;
    int half = t >> 7;             // 0/1: which row of the pair
    int tc = t & 127;              // column group
    #pragma unroll
    for (int it = 0; it < 4; it++){
        int g = blockIdx.x * 8 + it * 2 + half;   // 5184 rows total
        int b = g / (BTOT*KSEL);
        int rem = g - b*(BTOT*KSEL);
        int i = rem / KSEL, k = rem - i*KSEL;
        int src = g_topidx[i*KSEL + k];
        size_t row = (size_t)(b*HWSZ + src);
        float inv = g_rowinv[row];
        uint2 pk = ((const uint2*)&g_simEh[row*NTOK])[tc];
        __half2 h0 = *(__half2*)&pk.x, h1 = *(__half2*)&pk.y;
        float2 f0 = __half22float2(h0), f1 = __half22float2(h1);
        ((float4*)&outp[OUT_RES + (size_t)g*NTOK])[tc] =
            make_float4(f0.x*inv, f0.y*inv, f1.x*inv, f1.y*inv);
    }
}

// ---------------- launch ----------------
extern "C" void kernel_launch(void* const* d_in, const int* in_sizes, int n_in,
                              void* d_out, int out_size){
    const float* x   = (const float*)d_in[0];
    const float* DRp = (const float*)d_in[1];
    const float* ciw = (const float*)d_in[2];
    const float* cib = (const float*)d_in[3];
    const float* sw  = (const float*)d_in[4];
    const float* sb  = (const float*)d_in[5];
    const float* n1w = (const float*)d_in[6];
    const float* n1b = (const float*)d_in[7];
    const float* n2w = (const float*)d_in[8];
    const float* n2b = (const float*)d_in[9];
    const float* cow = (const float*)d_in[10];
    const float* cob = (const float*)d_in[11];
    float* out = (float*)d_out;

    cudaFuncSetAttribute(k_fused, cudaFuncAttributeMaxDynamicSharedMemorySize, SMEM_FUSED);

    k_prep_all <<<320, 384>>>(sw, ciw, cib, sb, cow, DRp, n2w, n2b);
    k_fused    <<<MROW/128, 256, SMEM_FUSED>>>(x, n1w, n1b, cob, out);
    k_topk_mask<<<BTOT, 1024>>>(out);
    k_gather   <<<BTOT*BTOT*KSEL/8, 256>>>(out);
}